// round 1
// baseline (speedup 1.0000x reference)
#include <cuda_runtime.h>

#define RR   128          // n_rows (attention length)
#define CC   256          // n_cols
#define EMB  768
#define NH   12
#define DKD  64
#define NT   (RR * CC)    // 32768 tokens (batch = 1)

// ---------------- scratch (allocation-free: __device__ globals) -------------
__device__ float g_Q[(size_t)CC * NH * RR * DKD];   // [c][h][i][d]
__device__ float g_K[(size_t)CC * NH * RR * DKD];
__device__ float g_V[(size_t)CC * NH * RR * DKD];
__device__ float g_ctx[(size_t)NT * EMB];           // [t][e]

// ---------------------------------------------------------------------------
// GEMM: out = (A @ W^T + bias) * scale
//   A: [32768, 768] row-major, W: [768, 768] row-major ([out,in] torch style)
//   attn_layout=1: write to [c][h][i][d] layout (for Q/K/V)
//   attn_layout=0: write plain [m][n]
// Tiles: 128x128 block, BK=16, 256 threads, 8x8 per thread. FFMA-bound.
// ---------------------------------------------------------------------------
__global__ __launch_bounds__(256) void gemm_kernel(
    const float* __restrict__ A, const float* __restrict__ W,
    const float* __restrict__ bias, float* __restrict__ out,
    float scale, int attn_layout)
{
    __shared__ float As[16][128];
    __shared__ float Bs[16][128];

    const int tid = threadIdx.x;
    const int tx  = tid & 15;
    const int ty  = tid >> 4;
    const int m0  = blockIdx.y << 7;
    const int n0  = blockIdx.x << 7;

    float acc[8][8];
#pragma unroll
    for (int i = 0; i < 8; i++)
#pragma unroll
        for (int j = 0; j < 8; j++) acc[i][j] = 0.f;

    const int rowA = tid >> 2;          // 0..63
    const int c4   = (tid & 3) << 2;    // 0,4,8,12

    for (int k0 = 0; k0 < EMB; k0 += 16) {
#pragma unroll
        for (int l = 0; l < 2; l++) {
            const int r = rowA + l * 64;
            float4 va = *(const float4*)&A[(size_t)(m0 + r) * EMB + k0 + c4];
            As[c4 + 0][r] = va.x; As[c4 + 1][r] = va.y;
            As[c4 + 2][r] = va.z; As[c4 + 3][r] = va.w;
            float4 vb = *(const float4*)&W[(size_t)(n0 + r) * EMB + k0 + c4];
            Bs[c4 + 0][r] = vb.x; Bs[c4 + 1][r] = vb.y;
            Bs[c4 + 2][r] = vb.z; Bs[c4 + 3][r] = vb.w;
        }
        __syncthreads();

#pragma unroll
        for (int kk = 0; kk < 16; kk++) {
            float a[8], b[8];
            *(float4*)&a[0] = *(const float4*)&As[kk][ty * 8];
            *(float4*)&a[4] = *(const float4*)&As[kk][ty * 8 + 4];
            *(float4*)&b[0] = *(const float4*)&Bs[kk][tx * 8];
            *(float4*)&b[4] = *(const float4*)&Bs[kk][tx * 8 + 4];
#pragma unroll
            for (int i = 0; i < 8; i++)
#pragma unroll
                for (int j = 0; j < 8; j++)
                    acc[i][j] += a[i] * b[j];
        }
        __syncthreads();
    }

#pragma unroll
    for (int i = 0; i < 8; i++) {
        const int m = m0 + ty * 8 + i;
#pragma unroll
        for (int j = 0; j < 8; j++) {
            const int o = n0 + tx * 8 + j;
            const float v = (acc[i][j] + bias[o]) * scale;
            if (attn_layout) {
                const int irow = m >> 8;      // t / 256
                const int c    = m & 255;     // t % 256
                const int h    = o >> 6;
                const int d    = o & 63;
                out[(((size_t)c * NH + h) * RR + irow) * DKD + d] = v;
            } else {
                out[(size_t)m * EMB + o] = v;
            }
        }
    }
}

// ---------------------------------------------------------------------------
// Attention per (col, head): S = Q K^T, mask, softmax, ctx = P V; write probs.
// 256 threads. Q row cached in registers; K/V in smem (pad 68 for aligned
// float4 + decent banking); S in smem (pad 129, conflict-free).
// ---------------------------------------------------------------------------
#define QPAD 65
#define KPAD 68
#define SPAD 129
#define ATTN_SMEM ((RR * QPAD + 2 * RR * KPAD + RR * SPAD) * sizeof(float))  // 168960 B

__global__ __launch_bounds__(256) void attn_kernel(
    const unsigned char* __restrict__ mask,
    float* __restrict__ probs, int write_probs)
{
    extern __shared__ float sm[];
    float* Qs = sm;                       // 128 x 65
    float* Ks = Qs + RR * QPAD;           // 128 x 68
    float* Vs = Ks + RR * KPAD;           // 128 x 68
    float* S  = Vs + RR * KPAD;           // 128 x 129

    const int c   = blockIdx.x;
    const int h   = blockIdx.y;
    const int tid = threadIdx.x;
    const size_t base = (((size_t)c * NH + h) * RR) * DKD;

    // load Q/K/V tiles (128x64 floats each)
    for (int g = tid; g < (RR * DKD) / 4; g += 256) {
        const int i  = g >> 4;
        const int d4 = (g & 15) << 2;
        float4 q = *(const float4*)(g_Q + base + ((size_t)g << 2));
        Qs[i * QPAD + d4 + 0] = q.x; Qs[i * QPAD + d4 + 1] = q.y;
        Qs[i * QPAD + d4 + 2] = q.z; Qs[i * QPAD + d4 + 3] = q.w;
        float4 k = *(const float4*)(g_K + base + ((size_t)g << 2));
        *(float4*)&Ks[i * KPAD + d4] = k;
        float4 v = *(const float4*)(g_V + base + ((size_t)g << 2));
        *(float4*)&Vs[i * KPAD + d4] = v;
    }
    __syncthreads();

    // Phase 1: scores. thread = (row i, j-half)
    {
        const int i  = tid >> 1;
        const int jb = (tid & 1) << 6;
        float q[64];
#pragma unroll
        for (int d = 0; d < 64; d++) q[d] = Qs[i * QPAD + d];

        for (int j = 0; j < 64; j++) {
            const float* kr = &Ks[(jb + j) * KPAD];
            float a = 0.f;
#pragma unroll
            for (int d4 = 0; d4 < 16; d4++) {
                float4 kv = *(const float4*)(kr + (d4 << 2));
                a += q[d4 * 4 + 0] * kv.x + q[d4 * 4 + 1] * kv.y
                   + q[d4 * 4 + 2] * kv.z + q[d4 * 4 + 3] * kv.w;
            }
            if (mask[(jb + j) * CC + c]) a = -10000.f;   // padding_mask[0, j, c]
            S[i * SPAD + jb + j] = a;
        }
    }
    __syncthreads();

    // Phase 2: row softmax (one thread per row)
    if (tid < RR) {
        const int i = tid;
        float m = -1e30f;
        for (int j = 0; j < RR; j++) m = fmaxf(m, S[i * SPAD + j]);
        float s = 0.f;
        for (int j = 0; j < RR; j++) {
            float e = __expf(S[i * SPAD + j] - m);
            S[i * SPAD + j] = e;
            s += e;
        }
        const float inv = 1.f / s;
        for (int j = 0; j < RR; j++) S[i * SPAD + j] *= inv;
    }
    __syncthreads();

    // probs out: [h][c][b=0][i][j]
    if (write_probs) {
        float* pb = probs + (((size_t)h * CC + c) * RR) * RR;
        for (int g = tid; g < RR * RR; g += 256)
            pb[g] = S[(g >> 7) * SPAD + (g & 127)];
    }

    // Phase 3: ctx = P @ V. thread = (row i, d-half of 32)
    {
        const int i  = tid >> 1;
        const int db = (tid & 1) << 5;
        float acc[32];
#pragma unroll
        for (int d = 0; d < 32; d++) acc[d] = 0.f;

        for (int j = 0; j < RR; j++) {
            const float p = S[i * SPAD + j];
            const float* vr = &Vs[j * KPAD + db];
#pragma unroll
            for (int d4 = 0; d4 < 8; d4++) {
                float4 vv = *(const float4*)(vr + (d4 << 2));
                acc[d4 * 4 + 0] += p * vv.x; acc[d4 * 4 + 1] += p * vv.y;
                acc[d4 * 4 + 2] += p * vv.z; acc[d4 * 4 + 3] += p * vv.w;
            }
        }
        float* cb = g_ctx + ((size_t)(i * CC + c)) * EMB + h * DKD + db;
#pragma unroll
        for (int d4 = 0; d4 < 8; d4++)
            *(float4*)(cb + (d4 << 2)) =
                make_float4(acc[d4 * 4 + 0], acc[d4 * 4 + 1],
                            acc[d4 * 4 + 2], acc[d4 * 4 + 3]);
    }
}

// ---------------------------------------------------------------------------
extern "C" void kernel_launch(void* const* d_in, const int* in_sizes, int n_in,
                              void* d_out, int out_size)
{
    const float*         x    = (const float*)d_in[0];
    const unsigned char* mask = (const unsigned char*)d_in[1];
    const float* Wq = (const float*)d_in[2];
    const float* bq = (const float*)d_in[3];
    const float* Wk = (const float*)d_in[4];
    const float* bk = (const float*)d_in[5];
    const float* Wv = (const float*)d_in[6];
    const float* bv = (const float*)d_in[7];
    const float* Wo = (const float*)d_in[8];
    const float* bo = (const float*)d_in[9];
    float* out = (float*)d_out;

    const long long OUT_E   = (long long)NT * EMB;            // 25,165,824
    const long long PROBS_E = (long long)NH * CC * RR * RR;   // 50,331,648

    float* probs = nullptr;
    int write_probs = 0;
    int do_output = 1;
    float* out_dst = out;
    if ((long long)out_size >= OUT_E + PROBS_E) {
        probs = out + OUT_E;
        write_probs = 1;
    } else if ((long long)out_size == PROBS_E) {
        probs = out;
        write_probs = 1;
        do_output = 0;
    }

    void *qp, *kp, *vp, *cp;
    cudaGetSymbolAddress(&qp, g_Q);
    cudaGetSymbolAddress(&kp, g_K);
    cudaGetSymbolAddress(&vp, g_V);
    cudaGetSymbolAddress(&cp, g_ctx);

    dim3 ggrid(EMB / 128, NT / 128);   // (6, 256)
    const float scaling = 0.125f;      // DK^-0.5

    gemm_kernel<<<ggrid, 256>>>(x, Wq, bq, (float*)qp, scaling, 1);
    gemm_kernel<<<ggrid, 256>>>(x, Wk, bk, (float*)kp, 1.0f, 1);
    gemm_kernel<<<ggrid, 256>>>(x, Wv, bv, (float*)vp, 1.0f, 1);

    static int smem_set = 0;
    if (!smem_set) {
        cudaFuncSetAttribute(attn_kernel,
                             cudaFuncAttributeMaxDynamicSharedMemorySize,
                             (int)ATTN_SMEM);
        smem_set = 1;
    }
    attn_kernel<<<dim3(CC, NH), 256, ATTN_SMEM>>>(mask, probs, write_probs);

    if (do_output)
        gemm_kernel<<<ggrid, 256>>>((const float*)cp, Wo, bo, out_dst, 1.0f, 0);
}

// round 3
// speedup vs baseline: 1.8947x; 1.8947x over previous
#include <cuda_runtime.h>
#include <cuda_bf16.h>
#include <cstdint>

#define RR   128
#define CC   256
#define EMB  768
#define NH   12
#define DKD  64
#define NT   (RR * CC)          // 32768 tokens

// ---------------- scratch (__device__ globals, allocation-free) -------------
__device__ float g_Q[(size_t)CC * NH * RR * DKD];   // [c][h][i][d]
__device__ float g_K[(size_t)CC * NH * RR * DKD];
__device__ float g_V[(size_t)CC * NH * RR * DKD];
__device__ float g_ctx[(size_t)NT * EMB];           // [t][e]

// ---------------------------- helpers --------------------------------------
__device__ __forceinline__ uint32_t smem_u32(const void* p) {
    uint32_t a;
    asm("{ .reg .u64 t; cvta.to.shared.u64 t, %1; cvt.u32.u64 %0, t; }"
        : "=r"(a) : "l"(p));
    return a;
}

__device__ __forceinline__ void ldsm4(uint32_t* r, uint32_t addr) {
    asm volatile("ldmatrix.sync.aligned.m8n8.x4.shared.b16 {%0,%1,%2,%3}, [%4];"
                 : "=r"(r[0]), "=r"(r[1]), "=r"(r[2]), "=r"(r[3]) : "r"(addr));
}

__device__ __forceinline__ void mma_bf16(float* c, const uint32_t* a,
                                         const uint32_t* b) {
    asm volatile(
        "mma.sync.aligned.m16n8k16.row.col.f32.bf16.bf16.f32 "
        "{%0,%1,%2,%3}, {%4,%5,%6,%7}, {%8,%9}, {%0,%1,%2,%3};"
        : "+f"(c[0]), "+f"(c[1]), "+f"(c[2]), "+f"(c[3])
        : "r"(a[0]), "r"(a[1]), "r"(a[2]), "r"(a[3]), "r"(b[0]), "r"(b[1]));
}

// ---------------------------------------------------------------------------
// Tensor-core GEMM with fused fp32 -> (hi,lo) bf16 split, 3-term product.
// out = (A @ W^T + bias) * scale
//   A: [32768, 768] fp32 row-major; W: [768, 768] fp32 row-major ([out, in]).
// CTA tile 128x128, BK=32, 8 warps (warp tile 32x64), m16n8k16 HMMA.
// ---------------------------------------------------------------------------
#define BM   128
#define BN   128
#define BK   32
#define SSTR 40     // smem row stride in bf16 elems (80 B: mult of 16, LDSM conflict-free)

__global__ __launch_bounds__(256, 2) void gemm_mma(
    const float* __restrict__ A, const float* __restrict__ W,
    const float* __restrict__ bias, float* __restrict__ out,
    float scale, int attn_layout)
{
    __shared__ __nv_bfloat16 sAh[BM * SSTR];
    __shared__ __nv_bfloat16 sAl[BM * SSTR];
    __shared__ __nv_bfloat16 sBh[BM * SSTR];
    __shared__ __nv_bfloat16 sBl[BM * SSTR];

    const int tid    = threadIdx.x;
    const int lane   = tid & 31;
    const int wid    = tid >> 5;
    const int warp_m = (wid & 3) << 5;    // 0,32,64,96
    const int warp_n = (wid >> 2) << 6;   // 0,64
    const int m0 = blockIdx.y << 7;
    const int n0 = blockIdx.x << 7;

    const uint32_t uAh = smem_u32(sAh);
    const uint32_t uAl = smem_u32(sAl);
    const uint32_t uBh = smem_u32(sBh);
    const uint32_t uBl = smem_u32(sBl);

    float acc[2][8][4];
#pragma unroll
    for (int mi = 0; mi < 2; mi++)
#pragma unroll
        for (int ni = 0; ni < 8; ni++)
#pragma unroll
            for (int q = 0; q < 4; q++) acc[mi][ni][q] = 0.f;

    // ldmatrix lane addressing (element offsets within a tile)
    const int a_r = lane & 15;               // row 0..15
    const int a_k = (lane >> 4) << 3;        // +0 / +8 in k
    const int b_n = (lane & 7) + ((lane >> 4) << 3);  // n-line 0..15
    const int b_k = ((lane >> 3) & 1) << 3;  // +0 / +8 in k

    const int l_row = tid >> 3;              // load phase: 2 rows per pass
    const int l_c4  = (tid & 7) << 2;        // fp32 col group (0..28 step 4)

    for (int k0 = 0; k0 < EMB; k0 += BK) {
        __syncthreads();   // previous tile fully consumed
        // ---- stage: load fp32, split to hi/lo bf16, store to smem ----
#pragma unroll
        for (int it = 0; it < 4; it++) {
            const int row = l_row + it * 32;
            float4 va = *(const float4*)(A + (size_t)(m0 + row) * EMB + k0 + l_c4);
            float4 vb = *(const float4*)(W + (size_t)(n0 + row) * EMB + k0 + l_c4);
            float a4[4] = {va.x, va.y, va.z, va.w};
            float b4[4] = {vb.x, vb.y, vb.z, vb.w};
            __nv_bfloat16 ah[4], al[4], bh[4], bl[4];
#pragma unroll
            for (int j = 0; j < 4; j++) {
                ah[j] = __float2bfloat16(a4[j]);
                al[j] = __float2bfloat16(a4[j] - __bfloat162float(ah[j]));
                bh[j] = __float2bfloat16(b4[j]);
                bl[j] = __float2bfloat16(b4[j] - __bfloat162float(bh[j]));
            }
            const int so = row * SSTR + l_c4;
            *(__nv_bfloat162*)&sAh[so]     = __halves2bfloat162(ah[0], ah[1]);
            *(__nv_bfloat162*)&sAh[so + 2] = __halves2bfloat162(ah[2], ah[3]);
            *(__nv_bfloat162*)&sAl[so]     = __halves2bfloat162(al[0], al[1]);
            *(__nv_bfloat162*)&sAl[so + 2] = __halves2bfloat162(al[2], al[3]);
            *(__nv_bfloat162*)&sBh[so]     = __halves2bfloat162(bh[0], bh[1]);
            *(__nv_bfloat162*)&sBh[so + 2] = __halves2bfloat162(bh[2], bh[3]);
            *(__nv_bfloat162*)&sBl[so]     = __halves2bfloat162(bl[0], bl[1]);
            *(__nv_bfloat162*)&sBl[so + 2] = __halves2bfloat162(bl[2], bl[3]);
        }
        __syncthreads();

        // ---- compute: 2 k16 steps ----
#pragma unroll
        for (int ks = 0; ks < 2; ks++) {
            const int kk = ks << 4;
            uint32_t aH[2][4], aL[2][4];
#pragma unroll
            for (int mi = 0; mi < 2; mi++) {
                const uint32_t off =
                    (uint32_t)((warp_m + mi * 16 + a_r) * SSTR + kk + a_k) * 2;
                ldsm4(aH[mi], uAh + off);
                ldsm4(aL[mi], uAl + off);
            }
#pragma unroll
            for (int np = 0; np < 4; np++) {
                uint32_t bH[4], bL[4];
                const uint32_t off =
                    (uint32_t)((warp_n + np * 16 + b_n) * SSTR + kk + b_k) * 2;
                ldsm4(bH, uBh + off);
                ldsm4(bL, uBl + off);
#pragma unroll
                for (int mi = 0; mi < 2; mi++) {
#pragma unroll
                    for (int s = 0; s < 2; s++) {
                        float* c = acc[mi][np * 2 + s];
                        mma_bf16(c, aH[mi], bH + 2 * s);
                        mma_bf16(c, aL[mi], bH + 2 * s);
                        mma_bf16(c, aH[mi], bL + 2 * s);
                    }
                }
            }
        }
    }

    // ---- epilogue ----
#pragma unroll
    for (int mi = 0; mi < 2; mi++) {
        const int rbase = m0 + warp_m + mi * 16 + (lane >> 2);
#pragma unroll
        for (int rr = 0; rr < 2; rr++) {
            const int m = rbase + rr * 8;
#pragma unroll
            for (int ni = 0; ni < 8; ni++) {
                const int col = n0 + warp_n + ni * 8 + ((lane & 3) << 1);
                const float2 bv = *(const float2*)&bias[col];
                const float v0 = (acc[mi][ni][rr * 2 + 0] + bv.x) * scale;
                const float v1 = (acc[mi][ni][rr * 2 + 1] + bv.y) * scale;
                size_t o;
                if (attn_layout) {
                    const int irow = m >> 8;
                    const int c    = m & 255;
                    const int h    = col >> 6;
                    const int d    = col & 63;
                    o = (((size_t)c * NH + h) * RR + irow) * DKD + d;
                } else {
                    o = (size_t)m * EMB + col;
                }
                *(float2*)&out[o] = make_float2(v0, v1);
            }
        }
    }
}

// ---------------------------------------------------------------------------
// Attention per (col, head): unchanged from round 1 (proven correct).
// ---------------------------------------------------------------------------
#define QPAD 65
#define KPAD 68
#define SPAD 129
#define ATTN_SMEM ((RR * QPAD + 2 * RR * KPAD + RR * SPAD) * sizeof(float))

__global__ __launch_bounds__(256) void attn_kernel(
    const unsigned char* __restrict__ mask,
    float* __restrict__ probs, int write_probs)
{
    extern __shared__ float sm[];
    float* Qs = sm;
    float* Ks = Qs + RR * QPAD;
    float* Vs = Ks + RR * KPAD;
    float* S  = Vs + RR * KPAD;

    const int c   = blockIdx.x;
    const int h   = blockIdx.y;
    const int tid = threadIdx.x;
    const size_t base = (((size_t)c * NH + h) * RR) * DKD;

    for (int g = tid; g < (RR * DKD) / 4; g += 256) {
        const int i  = g >> 4;
        const int d4 = (g & 15) << 2;
        float4 q = *(const float4*)(g_Q + base + ((size_t)g << 2));
        Qs[i * QPAD + d4 + 0] = q.x; Qs[i * QPAD + d4 + 1] = q.y;
        Qs[i * QPAD + d4 + 2] = q.z; Qs[i * QPAD + d4 + 3] = q.w;
        float4 k = *(const float4*)(g_K + base + ((size_t)g << 2));
        *(float4*)&Ks[i * KPAD + d4] = k;
        float4 v = *(const float4*)(g_V + base + ((size_t)g << 2));
        *(float4*)&Vs[i * KPAD + d4] = v;
    }
    __syncthreads();

    {
        const int i  = tid >> 1;
        const int jb = (tid & 1) << 6;
        float q[64];
#pragma unroll
        for (int d = 0; d < 64; d++) q[d] = Qs[i * QPAD + d];

        for (int j = 0; j < 64; j++) {
            const float* kr = &Ks[(jb + j) * KPAD];
            float a = 0.f;
#pragma unroll
            for (int d4 = 0; d4 < 16; d4++) {
                float4 kv = *(const float4*)(kr + (d4 << 2));
                a += q[d4 * 4 + 0] * kv.x + q[d4 * 4 + 1] * kv.y
                   + q[d4 * 4 + 2] * kv.z + q[d4 * 4 + 3] * kv.w;
            }
            if (mask[(jb + j) * CC + c]) a = -10000.f;
            S[i * SPAD + jb + j] = a;
        }
    }
    __syncthreads();

    if (tid < RR) {
        const int i = tid;
        float m = -1e30f;
        for (int j = 0; j < RR; j++) m = fmaxf(m, S[i * SPAD + j]);
        float s = 0.f;
        for (int j = 0; j < RR; j++) {
            float e = __expf(S[i * SPAD + j] - m);
            S[i * SPAD + j] = e;
            s += e;
        }
        const float inv = 1.f / s;
        for (int j = 0; j < RR; j++) S[i * SPAD + j] *= inv;
    }
    __syncthreads();

    if (write_probs) {
        float* pb = probs + (((size_t)h * CC + c) * RR) * RR;
        for (int g = tid; g < RR * RR; g += 256)
            pb[g] = S[(g >> 7) * SPAD + (g & 127)];
    }

    {
        const int i  = tid >> 1;
        const int db = (tid & 1) << 5;
        float acc[32];
#pragma unroll
        for (int d = 0; d < 32; d++) acc[d] = 0.f;

        for (int j = 0; j < RR; j++) {
            const float p = S[i * SPAD + j];
            const float* vr = &Vs[j * KPAD + db];
#pragma unroll
            for (int d4 = 0; d4 < 8; d4++) {
                float4 vv = *(const float4*)(vr + (d4 << 2));
                acc[d4 * 4 + 0] += p * vv.x; acc[d4 * 4 + 1] += p * vv.y;
                acc[d4 * 4 + 2] += p * vv.z; acc[d4 * 4 + 3] += p * vv.w;
            }
        }
        float* cb = g_ctx + ((size_t)(i * CC + c)) * EMB + h * DKD + db;
#pragma unroll
        for (int d4 = 0; d4 < 8; d4++)
            *(float4*)(cb + (d4 << 2)) =
                make_float4(acc[d4 * 4 + 0], acc[d4 * 4 + 1],
                            acc[d4 * 4 + 2], acc[d4 * 4 + 3]);
    }
}

// ---------------------------------------------------------------------------
extern "C" void kernel_launch(void* const* d_in, const int* in_sizes, int n_in,
                              void* d_out, int out_size)
{
    const float*         x    = (const float*)d_in[0];
    const unsigned char* mask = (const unsigned char*)d_in[1];
    const float* Wq = (const float*)d_in[2];
    const float* bq = (const float*)d_in[3];
    const float* Wk = (const float*)d_in[4];
    const float* bk = (const float*)d_in[5];
    const float* Wv = (const float*)d_in[6];
    const float* bv = (const float*)d_in[7];
    const float* Wo = (const float*)d_in[8];
    const float* bo = (const float*)d_in[9];
    float* out = (float*)d_out;

    const long long OUT_E   = (long long)NT * EMB;
    const long long PROBS_E = (long long)NH * CC * RR * RR;

    float* probs = nullptr;
    int write_probs = 0;
    int do_output = 1;
    if ((long long)out_size >= OUT_E + PROBS_E) {
        probs = out + OUT_E;
        write_probs = 1;
    } else if ((long long)out_size == PROBS_E) {
        probs = out;
        write_probs = 1;
        do_output = 0;
    }

    void *qp, *kp, *vp, *cp;
    cudaGetSymbolAddress(&qp, g_Q);
    cudaGetSymbolAddress(&kp, g_K);
    cudaGetSymbolAddress(&vp, g_V);
    cudaGetSymbolAddress(&cp, g_ctx);

    static int attr_set = 0;
    if (!attr_set) {
        cudaFuncSetAttribute(attn_kernel,
                             cudaFuncAttributeMaxDynamicSharedMemorySize,
                             (int)ATTN_SMEM);
        attr_set = 1;
    }

    dim3 ggrid(EMB / 128, NT / 128);   // (6, 256)
    const float scaling = 0.125f;      // DK^-0.5

    gemm_mma<<<ggrid, 256>>>(x, Wq, bq, (float*)qp, scaling, 1);
    gemm_mma<<<ggrid, 256>>>(x, Wk, bk, (float*)kp, 1.0f, 1);
    gemm_mma<<<ggrid, 256>>>(x, Wv, bv, (float*)vp, 1.0f, 1);

    attn_kernel<<<dim3(CC, NH), 256, ATTN_SMEM>>>(mask, probs, write_probs);

    if (do_output)
        gemm_mma<<<ggrid, 256>>>((const float*)cp, Wo, bo, out, 1.0f, 0);
}

// round 6
// speedup vs baseline: 2.3925x; 1.2627x over previous
#include <cuda_runtime.h>
#include <cuda_bf16.h>
#include <cstdint>

#define RR   128
#define CC   256
#define EMB  768
#define NH   12
#define DKD  64
#define NT   (RR * CC)          // 32768 tokens

typedef __nv_bfloat16 bf16;

// ---------------- scratch (__device__ globals, allocation-free) -------------
__device__ bf16 g_Xh[(size_t)NT * EMB];
__device__ bf16 g_Xl[(size_t)NT * EMB];
__device__ bf16 g_Wh[4][(size_t)EMB * EMB];
__device__ bf16 g_Wl[4][(size_t)EMB * EMB];
__device__ bf16 g_Qh[(size_t)CC * NH * RR * DKD];   // [c][h][i][d]
__device__ bf16 g_Ql[(size_t)CC * NH * RR * DKD];
__device__ bf16 g_Kh[(size_t)CC * NH * RR * DKD];
__device__ bf16 g_Kl[(size_t)CC * NH * RR * DKD];
__device__ bf16 g_Vth[(size_t)CC * NH * DKD * RR];  // [c][h][d][i] (transposed)
__device__ bf16 g_Vtl[(size_t)CC * NH * DKD * RR];
__device__ bf16 g_Ch[(size_t)NT * EMB];             // ctx hi/lo [t][e]
__device__ bf16 g_Cl[(size_t)NT * EMB];

// ---------------------------- helpers --------------------------------------
__device__ __forceinline__ uint32_t smem_u32(const void* p) {
    uint32_t a;
    asm("{ .reg .u64 t; cvta.to.shared.u64 t, %1; cvt.u32.u64 %0, t; }"
        : "=r"(a) : "l"(p));
    return a;
}
__device__ __forceinline__ void ldsm4(uint32_t* r, uint32_t addr) {
    asm volatile("ldmatrix.sync.aligned.m8n8.x4.shared.b16 {%0,%1,%2,%3}, [%4];"
                 : "=r"(r[0]), "=r"(r[1]), "=r"(r[2]), "=r"(r[3]) : "r"(addr));
}
__device__ __forceinline__ void mma_bf16(float* c, const uint32_t* a,
                                         const uint32_t* b) {
    asm volatile(
        "mma.sync.aligned.m16n8k16.row.col.f32.bf16.bf16.f32 "
        "{%0,%1,%2,%3}, {%4,%5,%6,%7}, {%8,%9}, {%0,%1,%2,%3};"
        : "+f"(c[0]), "+f"(c[1]), "+f"(c[2]), "+f"(c[3])
        : "r"(a[0]), "r"(a[1]), "r"(a[2]), "r"(a[3]), "r"(b[0]), "r"(b[1]));
}
#define CP_ASYNC(dst, src) \
    asm volatile("cp.async.cg.shared.global [%0], [%1], 16;" \
                 :: "r"(dst), "l"(src) : "memory")
#define CP_COMMIT() asm volatile("cp.async.commit_group;" ::: "memory")
#define CP_WAIT(n)  asm volatile("cp.async.wait_group %0;" :: "n"(n) : "memory")

__device__ __forceinline__ void split1(float v, bf16& h, bf16& l) {
    h = __float2bfloat16(v);
    l = __float2bfloat16(v - __bfloat162float(h));
}

// ---------------------------------------------------------------------------
// fp32 -> (hi, lo) bf16 split
// ---------------------------------------------------------------------------
__global__ __launch_bounds__(256) void split_kernel(
    const float* __restrict__ src, bf16* __restrict__ hi,
    bf16* __restrict__ lo, int n4)
{
    int i = blockIdx.x * blockDim.x + threadIdx.x;
    if (i >= n4) return;
    float4 v = ((const float4*)src)[i];
    float a[4] = {v.x, v.y, v.z, v.w};
    bf16 h[4], l[4];
#pragma unroll
    for (int j = 0; j < 4; j++) split1(a[j], h[j], l[j]);
    ((__nv_bfloat162*)hi)[2 * i + 0] = __halves2bfloat162(h[0], h[1]);
    ((__nv_bfloat162*)hi)[2 * i + 1] = __halves2bfloat162(h[2], h[3]);
    ((__nv_bfloat162*)lo)[2 * i + 0] = __halves2bfloat162(l[0], l[1]);
    ((__nv_bfloat162*)lo)[2 * i + 1] = __halves2bfloat162(l[2], l[3]);
}

// ---------------------------------------------------------------------------
// Pipelined bf16 tensor-core GEMM, 3-term hi/lo product.
// C = (Ah+Al)(Bh+Bl)^T ~ AhBh + AlBh + AhBl; + bias, * scale.
// modes: 0 -> fp32 out [m][EMB]
//        1 -> bf16 hi/lo out [c][h][i][d]      (Q, K)
//        2 -> bf16 hi/lo out [c][h][d][i]      (V, transposed)
// ---------------------------------------------------------------------------
#define BK        32
#define SSTR      40          // smem row stride (bf16 elems) = 80 B
#define TILE_B    (128 * SSTR * 2)          // 10240 B
#define STAGE_B   (4 * TILE_B)              // 40960 B
#define GEMM_SMEM (2 * STAGE_B)             // 81920 B

__global__ __launch_bounds__(256, 2) void gemm_mma(
    const bf16* __restrict__ Ah, const bf16* __restrict__ Al,
    const bf16* __restrict__ Bh, const bf16* __restrict__ Bl,
    const float* __restrict__ bias,
    float* __restrict__ outF, bf16* __restrict__ outH, bf16* __restrict__ outL,
    float scale, int mode)
{
    extern __shared__ char dsm[];
    const uint32_t u0 = smem_u32(dsm);

    const int tid    = threadIdx.x;
    const int lane   = tid & 31;
    const int wid    = tid >> 5;
    const int warp_m = (wid & 3) << 5;
    const int warp_n = (wid >> 2) << 6;
    const int m0 = blockIdx.y << 7;
    const int n0 = blockIdx.x << 7;

    float acc[2][8][4];
#pragma unroll
    for (int mi = 0; mi < 2; mi++)
#pragma unroll
        for (int ni = 0; ni < 8; ni++)
#pragma unroll
            for (int q = 0; q < 4; q++) acc[mi][ni][q] = 0.f;

    const int a_r = lane & 15;
    const int a_k = (lane >> 4) << 3;
    const int b_n = (lane & 7) + ((lane >> 4) << 3);
    const int b_k = ((lane >> 3) & 1) << 3;

    const int f_row = tid >> 2;        // 0..63
    const int f_c16 = tid & 3;

#define FILL(stage, k0) do {                                                   \
        const uint32_t sb = u0 + (stage) * STAGE_B;                            \
        _Pragma("unroll")                                                      \
        for (int t = 0; t < 4; t++) {                                          \
            const bf16* sp = (t == 0) ? Ah : (t == 1) ? Al : (t == 2) ? Bh : Bl;\
            const int rb = (t < 2) ? m0 : n0;                                  \
            _Pragma("unroll")                                                  \
            for (int sub = 0; sub < 2; sub++) {                                \
                const int row = f_row + sub * 64;                              \
                CP_ASYNC(sb + t * TILE_B + row * (SSTR * 2) + f_c16 * 16,      \
                         sp + (size_t)(rb + row) * EMB + (k0) + f_c16 * 8);    \
            }                                                                  \
        }                                                                      \
        CP_COMMIT();                                                           \
    } while (0)

    FILL(0, 0);

    for (int s = 0; s < EMB / BK; s++) {
        if (s < EMB / BK - 1) { FILL((s + 1) & 1, (s + 1) * BK); CP_WAIT(1); }
        else                  { CP_WAIT(0); }
        __syncthreads();

        const uint32_t sb  = u0 + (s & 1) * STAGE_B;
        const uint32_t uAh = sb;
        const uint32_t uAl = sb + TILE_B;
        const uint32_t uBh = sb + 2 * TILE_B;
        const uint32_t uBl = sb + 3 * TILE_B;

#pragma unroll
        for (int ks = 0; ks < 2; ks++) {
            const int kk = ks << 4;
            uint32_t aH[2][4], aL[2][4];
#pragma unroll
            for (int mi = 0; mi < 2; mi++) {
                const uint32_t off =
                    (uint32_t)((warp_m + mi * 16 + a_r) * SSTR + kk + a_k) * 2;
                ldsm4(aH[mi], uAh + off);
                ldsm4(aL[mi], uAl + off);
            }
#pragma unroll
            for (int np = 0; np < 4; np++) {
                uint32_t bH[4], bL[4];
                const uint32_t off =
                    (uint32_t)((warp_n + np * 16 + b_n) * SSTR + kk + b_k) * 2;
                ldsm4(bH, uBh + off);
                ldsm4(bL, uBl + off);
#pragma unroll
                for (int mi = 0; mi < 2; mi++) {
#pragma unroll
                    for (int ss = 0; ss < 2; ss++) {
                        float* c = acc[mi][np * 2 + ss];
                        mma_bf16(c, aH[mi], bH + 2 * ss);
                        mma_bf16(c, aL[mi], bH + 2 * ss);
                        mma_bf16(c, aH[mi], bL + 2 * ss);
                    }
                }
            }
        }
        __syncthreads();
    }

    // ---- epilogue ----
#pragma unroll
    for (int mi = 0; mi < 2; mi++) {
#pragma unroll
        for (int rr = 0; rr < 2; rr++) {
            const int m = m0 + warp_m + mi * 16 + rr * 8 + (lane >> 2);
            const int irow = m >> 8;           // token -> (i, c)
            const int ccol = m & 255;
#pragma unroll
            for (int ni = 0; ni < 8; ni++) {
                const int col = n0 + warp_n + ni * 8 + ((lane & 3) << 1);
                const float2 bv = *(const float2*)&bias[col];
                const float v0 = (acc[mi][ni][rr * 2 + 0] + bv.x) * scale;
                const float v1 = (acc[mi][ni][rr * 2 + 1] + bv.y) * scale;
                if (mode == 0) {
                    *(float2*)&outF[(size_t)m * EMB + col] = make_float2(v0, v1);
                } else {
                    bf16 h0, l0, h1, l1;
                    split1(v0, h0, l0); split1(v1, h1, l1);
                    const int hh = col >> 6;
                    const int dd = col & 63;
                    if (mode == 1) {
                        const size_t o = (((size_t)ccol * NH + hh) * RR + irow) * DKD + dd;
                        *(__nv_bfloat162*)&outH[o] = __halves2bfloat162(h0, h1);
                        *(__nv_bfloat162*)&outL[o] = __halves2bfloat162(l0, l1);
                    } else {
                        const size_t o = (((size_t)ccol * NH + hh) * DKD + dd) * RR + irow;
                        outH[o] = h0; outH[o + RR] = h1;
                        outL[o] = l0; outL[o + RR] = l1;
                    }
                }
            }
        }
    }
}

// ---------------------------------------------------------------------------
// Tensor-core attention per (col, head).
// S = QK^T (3-term), fp32 smem softmax, probs out, P.V (3-term), ctx hi/lo out.
// ---------------------------------------------------------------------------
#define QS 72     // stride for 64-wide bf16 tiles (144 B)
#define PS 136    // stride for 128-wide bf16 tiles (272 B)
#define SP 130    // EVEN: float2 accesses to S are 8B-aligned (R4 bug was SP=129)

#define AOFF_QH  0
#define AOFF_QL  (AOFF_QH + 128 * QS * 2)    // 18432
#define AOFF_KH  (AOFF_QL + 128 * QS * 2)    // 36864
#define AOFF_KL  (AOFF_KH + 128 * QS * 2)    // 55296
#define AOFF_VH  (AOFF_KL + 128 * QS * 2)    // 73728
#define AOFF_VL  (AOFF_VH + 64 * PS * 2)     // 91136
#define AOFF_S   (AOFF_VL + 64 * PS * 2)     // 108544
#define AOFF_MK  (AOFF_S + 128 * SP * 4)     // 175104
#define ATTN_SMEM (AOFF_MK + 128)            // 175232
#define AOFF_PH  0                            // overlay on Q/K region
#define AOFF_PL  (AOFF_PH + 128 * PS * 2)    // 34816 (fits in 73728)

__global__ __launch_bounds__(256) void attn_mma(
    const bf16* __restrict__ qh, const bf16* __restrict__ ql,
    const bf16* __restrict__ kh, const bf16* __restrict__ kl,
    const bf16* __restrict__ vth, const bf16* __restrict__ vtl,
    const unsigned char* __restrict__ mask,
    float* __restrict__ probs, int write_probs)
{
    extern __shared__ char dsm[];
    const uint32_t u0 = smem_u32(dsm);
    float* S = (float*)(dsm + AOFF_S);
    unsigned char* sMask = (unsigned char*)(dsm + AOFF_MK);

    const int c   = blockIdx.x;
    const int h   = blockIdx.y;
    const int tid = threadIdx.x;
    const int lane = tid & 31;
    const int wid  = tid >> 5;
    const size_t base = (((size_t)c * NH + h) * RR) * DKD;   // same count for Vt

    // ---- load tiles via cp.async ----
    {
        const int row_q = tid >> 1;
        const int c16_q = tid & 1;
        const bf16* srcs[4] = {qh, ql, kh, kl};
        const uint32_t dsts[4] = {u0 + AOFF_QH, u0 + AOFF_QL,
                                  u0 + AOFF_KH, u0 + AOFF_KL};
#pragma unroll
        for (int t = 0; t < 4; t++) {
#pragma unroll
            for (int sub = 0; sub < 4; sub++) {
                const int cid = sub * 2 + c16_q;
                CP_ASYNC(dsts[t] + row_q * (QS * 2) + cid * 16,
                         srcs[t] + base + (size_t)row_q * DKD + cid * 8);
            }
        }
        const int row_v = tid >> 2;
        const int c4_v  = tid & 3;
#pragma unroll
        for (int sub = 0; sub < 4; sub++) {
            const int cid = sub * 4 + c4_v;
            CP_ASYNC(u0 + AOFF_VH + row_v * (PS * 2) + cid * 16,
                     vth + base + (size_t)row_v * RR + cid * 8);
            CP_ASYNC(u0 + AOFF_VL + row_v * (PS * 2) + cid * 16,
                     vtl + base + (size_t)row_v * RR + cid * 8);
        }
        CP_COMMIT();
        if (tid < 128) sMask[tid] = mask[(size_t)tid * CC + c];
        CP_WAIT(0);
    }
    __syncthreads();

    const int a_r = lane & 15;
    const int a_k = (lane >> 4) << 3;
    const int b_n = (lane & 7) + ((lane >> 4) << 3);
    const int b_k = ((lane >> 3) & 1) << 3;
    const int warp_m = (wid & 3) << 5;

    // ---- S = Q K^T (M=128, N=128, K=64) ----
    {
        const int warp_n = (wid >> 2) << 6;
        float acc[2][8][4];
#pragma unroll
        for (int mi = 0; mi < 2; mi++)
#pragma unroll
            for (int ni = 0; ni < 8; ni++)
#pragma unroll
                for (int q = 0; q < 4; q++) acc[mi][ni][q] = 0.f;

#pragma unroll
        for (int ks = 0; ks < 4; ks++) {
            const int kk = ks << 4;
            uint32_t aH[2][4], aL[2][4];
#pragma unroll
            for (int mi = 0; mi < 2; mi++) {
                const uint32_t off =
                    (uint32_t)((warp_m + mi * 16 + a_r) * QS + kk + a_k) * 2;
                ldsm4(aH[mi], u0 + AOFF_QH + off);
                ldsm4(aL[mi], u0 + AOFF_QL + off);
            }
#pragma unroll
            for (int np = 0; np < 4; np++) {
                uint32_t bH[4], bL[4];
                const uint32_t off =
                    (uint32_t)((warp_n + np * 16 + b_n) * QS + kk + b_k) * 2;
                ldsm4(bH, u0 + AOFF_KH + off);
                ldsm4(bL, u0 + AOFF_KL + off);
#pragma unroll
                for (int mi = 0; mi < 2; mi++) {
#pragma unroll
                    for (int ss = 0; ss < 2; ss++) {
                        float* cp = acc[mi][np * 2 + ss];
                        mma_bf16(cp, aH[mi], bH + 2 * ss);
                        mma_bf16(cp, aL[mi], bH + 2 * ss);
                        mma_bf16(cp, aH[mi], bL + 2 * ss);
                    }
                }
            }
        }
#pragma unroll
        for (int mi = 0; mi < 2; mi++) {
#pragma unroll
            for (int rr = 0; rr < 2; rr++) {
                const int row = warp_m + mi * 16 + rr * 8 + (lane >> 2);
#pragma unroll
                for (int ni = 0; ni < 8; ni++) {
                    const int col = warp_n + ni * 8 + ((lane & 3) << 1);
                    float v0 = acc[mi][ni][rr * 2 + 0];
                    float v1 = acc[mi][ni][rr * 2 + 1];
                    if (sMask[col])     v0 = -10000.f;
                    if (sMask[col + 1]) v1 = -10000.f;
                    *(float2*)&S[row * SP + col] = make_float2(v0, v1);
                }
            }
        }
    }
    __syncthreads();

    // ---- softmax (one thread per row; proven) ----
    if (tid < RR) {
        const int i = tid;
        float m = -1e30f;
        for (int j = 0; j < RR; j++) m = fmaxf(m, S[i * SP + j]);
        float s = 0.f;
        for (int j = 0; j < RR; j++) {
            float e = __expf(S[i * SP + j] - m);
            S[i * SP + j] = e;
            s += e;
        }
        const float inv = 1.f / s;
        for (int j = 0; j < RR; j++) S[i * SP + j] *= inv;
    }
    __syncthreads();

    if (write_probs) {
        float* pb = probs + (((size_t)h * CC + c) * RR) * RR;
        for (int g = tid; g < RR * RR; g += 256)
            pb[g] = S[(g >> 7) * SP + (g & 127)];
    }

    // ---- convert P -> hi/lo bf16 (overlay on Q/K smem) ----
    {
        bf16* Ph = (bf16*)(dsm + AOFF_PH);
        bf16* Pl = (bf16*)(dsm + AOFF_PL);
        for (int p = tid; p < 128 * 64; p += 256) {
            const int i  = p >> 6;
            const int j2 = (p & 63) << 1;
            float2 v = *(const float2*)&S[i * SP + j2];
            bf16 h0, l0, h1, l1;
            split1(v.x, h0, l0); split1(v.y, h1, l1);
            *(__nv_bfloat162*)&Ph[i * PS + j2] = __halves2bfloat162(h0, h1);
            *(__nv_bfloat162*)&Pl[i * PS + j2] = __halves2bfloat162(l0, l1);
        }
    }
    __syncthreads();

    // ---- ctx = P V (M=128, N=64, K=128) ----
    {
        const int warp_nd = (wid >> 2) << 5;   // 0 / 32 (d dimension)
        float acc[2][4][4];
#pragma unroll
        for (int mi = 0; mi < 2; mi++)
#pragma unroll
            for (int ni = 0; ni < 4; ni++)
#pragma unroll
                for (int q = 0; q < 4; q++) acc[mi][ni][q] = 0.f;

#pragma unroll
        for (int ks = 0; ks < 8; ks++) {
            const int kk = ks << 4;
            uint32_t aH[2][4], aL[2][4];
#pragma unroll
            for (int mi = 0; mi < 2; mi++) {
                const uint32_t off =
                    (uint32_t)((warp_m + mi * 16 + a_r) * PS + kk + a_k) * 2;
                ldsm4(aH[mi], u0 + AOFF_PH + off);
                ldsm4(aL[mi], u0 + AOFF_PL + off);
            }
#pragma unroll
            for (int np = 0; np < 2; np++) {
                uint32_t bH[4], bL[4];
                const uint32_t off =
                    (uint32_t)((warp_nd + np * 16 + b_n) * PS + kk + b_k) * 2;
                ldsm4(bH, u0 + AOFF_VH + off);
                ldsm4(bL, u0 + AOFF_VL + off);
#pragma unroll
                for (int mi = 0; mi < 2; mi++) {
#pragma unroll
                    for (int ss = 0; ss < 2; ss++) {
                        float* cp = acc[mi][np * 2 + ss];
                        mma_bf16(cp, aH[mi], bH + 2 * ss);
                        mma_bf16(cp, aH[mi], bL + 2 * ss);
                        mma_bf16(cp, aL[mi], bH + 2 * ss);
                    }
                }
            }
        }
#pragma unroll
        for (int mi = 0; mi < 2; mi++) {
#pragma unroll
            for (int rr = 0; rr < 2; rr++) {
                const int i = warp_m + mi * 16 + rr * 8 + (lane >> 2);
                const size_t tok = (size_t)i * CC + c;
#pragma unroll
                for (int ni = 0; ni < 4; ni++) {
                    const int d = warp_nd + ni * 8 + ((lane & 3) << 1);
                    const float v0 = acc[mi][ni][rr * 2 + 0];
                    const float v1 = acc[mi][ni][rr * 2 + 1];
                    bf16 h0, l0, h1, l1;
                    split1(v0, h0, l0); split1(v1, h1, l1);
                    const size_t o = tok * EMB + h * DKD + d;
                    *(__nv_bfloat162*)&g_Ch[o] = __halves2bfloat162(h0, h1);
                    *(__nv_bfloat162*)&g_Cl[o] = __halves2bfloat162(l0, l1);
                }
            }
        }
    }
}

// ---------------------------------------------------------------------------
extern "C" void kernel_launch(void* const* d_in, const int* in_sizes, int n_in,
                              void* d_out, int out_size)
{
    const float*         x    = (const float*)d_in[0];
    const unsigned char* mask = (const unsigned char*)d_in[1];
    const float* Wq = (const float*)d_in[2];
    const float* bq = (const float*)d_in[3];
    const float* Wk = (const float*)d_in[4];
    const float* bk = (const float*)d_in[5];
    const float* Wv = (const float*)d_in[6];
    const float* bv = (const float*)d_in[7];
    const float* Wo = (const float*)d_in[8];
    const float* bo = (const float*)d_in[9];
    float* out = (float*)d_out;

    const long long OUT_E   = (long long)NT * EMB;
    const long long PROBS_E = (long long)NH * CC * RR * RR;

    float* probs = nullptr;
    int write_probs = 0;
    int do_output = 1;
    if ((long long)out_size >= OUT_E + PROBS_E) {
        probs = out + OUT_E;
        write_probs = 1;
    } else if ((long long)out_size == PROBS_E) {
        probs = out;
        write_probs = 1;
        do_output = 0;
    }

    void *xh, *xl, *wh, *wl, *qh_, *ql_, *kh_, *kl_, *vh_, *vl_, *ch, *cl;
    cudaGetSymbolAddress(&xh, g_Xh);  cudaGetSymbolAddress(&xl, g_Xl);
    cudaGetSymbolAddress(&wh, g_Wh);  cudaGetSymbolAddress(&wl, g_Wl);
    cudaGetSymbolAddress(&qh_, g_Qh); cudaGetSymbolAddress(&ql_, g_Ql);
    cudaGetSymbolAddress(&kh_, g_Kh); cudaGetSymbolAddress(&kl_, g_Kl);
    cudaGetSymbolAddress(&vh_, g_Vth); cudaGetSymbolAddress(&vl_, g_Vtl);
    cudaGetSymbolAddress(&ch, g_Ch);  cudaGetSymbolAddress(&cl, g_Cl);

    bf16* Xh = (bf16*)xh; bf16* Xl = (bf16*)xl;
    bf16* Wh = (bf16*)wh; bf16* Wl = (bf16*)wl;
    bf16* Ch = (bf16*)ch; bf16* Cl = (bf16*)cl;
    const size_t WSZ = (size_t)EMB * EMB;

    static int attr_set = 0;
    if (!attr_set) {
        cudaFuncSetAttribute(gemm_mma,
                             cudaFuncAttributeMaxDynamicSharedMemorySize, GEMM_SMEM);
        cudaFuncSetAttribute(attn_mma,
                             cudaFuncAttributeMaxDynamicSharedMemorySize, ATTN_SMEM);
        attr_set = 1;
    }

    // splits
    split_kernel<<<(NT * EMB / 4 + 255) / 256, 256>>>(x, Xh, Xl, NT * EMB / 4);
    split_kernel<<<(int)(WSZ / 4 + 255) / 256, 256>>>(Wq, Wh + 0 * WSZ, Wl + 0 * WSZ, (int)(WSZ / 4));
    split_kernel<<<(int)(WSZ / 4 + 255) / 256, 256>>>(Wk, Wh + 1 * WSZ, Wl + 1 * WSZ, (int)(WSZ / 4));
    split_kernel<<<(int)(WSZ / 4 + 255) / 256, 256>>>(Wv, Wh + 2 * WSZ, Wl + 2 * WSZ, (int)(WSZ / 4));
    split_kernel<<<(int)(WSZ / 4 + 255) / 256, 256>>>(Wo, Wh + 3 * WSZ, Wl + 3 * WSZ, (int)(WSZ / 4));

    dim3 ggrid(EMB / 128, NT / 128);   // (6, 256)
    const float scaling = 0.125f;

    gemm_mma<<<ggrid, 256, GEMM_SMEM>>>(Xh, Xl, Wh + 0 * WSZ, Wl + 0 * WSZ, bq,
                                        nullptr, (bf16*)qh_, (bf16*)ql_, scaling, 1);
    gemm_mma<<<ggrid, 256, GEMM_SMEM>>>(Xh, Xl, Wh + 1 * WSZ, Wl + 1 * WSZ, bk,
                                        nullptr, (bf16*)kh_, (bf16*)kl_, 1.0f, 1);
    gemm_mma<<<ggrid, 256, GEMM_SMEM>>>(Xh, Xl, Wh + 2 * WSZ, Wl + 2 * WSZ, bv,
                                        nullptr, (bf16*)vh_, (bf16*)vl_, 1.0f, 2);

    attn_mma<<<dim3(CC, NH), 256, ATTN_SMEM>>>(
        (const bf16*)qh_, (const bf16*)ql_, (const bf16*)kh_, (const bf16*)kl_,
        (const bf16*)vh_, (const bf16*)vl_, mask, probs, write_probs);

    if (do_output)
        gemm_mma<<<ggrid, 256, GEMM_SMEM>>>(Ch, Cl, Wh + 3 * WSZ, Wl + 3 * WSZ, bo,
                                            out, nullptr, nullptr, 1.0f, 0);
}

// round 9
// speedup vs baseline: 2.6720x; 1.1168x over previous
#include <cuda_runtime.h>
#include <cuda_bf16.h>
#include <cstdint>

#define RR   128
#define CC   256
#define EMB  768
#define NH   12
#define DKD  64
#define NT   (RR * CC)          // 32768 tokens

typedef __nv_bfloat16 bf16;

// ---------------- scratch (__device__ globals, allocation-free) -------------
__device__ bf16 g_Xh[(size_t)NT * EMB];
__device__ bf16 g_Xl[(size_t)NT * EMB];
__device__ bf16 g_Wh[4][(size_t)EMB * EMB];
__device__ bf16 g_Wl[4][(size_t)EMB * EMB];
__device__ bf16 g_Qh[(size_t)CC * NH * RR * DKD];   // [c][h][i][d]
__device__ bf16 g_Ql[(size_t)CC * NH * RR * DKD];
__device__ bf16 g_Kh[(size_t)CC * NH * RR * DKD];
__device__ bf16 g_Kl[(size_t)CC * NH * RR * DKD];
__device__ bf16 g_Vth[(size_t)CC * NH * DKD * RR];  // [c][h][d][i] (transposed)
__device__ bf16 g_Vtl[(size_t)CC * NH * DKD * RR];
__device__ bf16 g_Ch[(size_t)NT * EMB];             // ctx hi/lo [t][e]
__device__ bf16 g_Cl[(size_t)NT * EMB];

// ---------------------------- helpers --------------------------------------
__device__ __forceinline__ uint32_t smem_u32(const void* p) {
    uint32_t a;
    asm("{ .reg .u64 t; cvta.to.shared.u64 t, %1; cvt.u32.u64 %0, t; }"
        : "=r"(a) : "l"(p));
    return a;
}
__device__ __forceinline__ void ldsm4(uint32_t* r, uint32_t addr) {
    asm volatile("ldmatrix.sync.aligned.m8n8.x4.shared.b16 {%0,%1,%2,%3}, [%4];"
                 : "=r"(r[0]), "=r"(r[1]), "=r"(r[2]), "=r"(r[3]) : "r"(addr));
}
__device__ __forceinline__ void mma_bf16(float* c, const uint32_t* a,
                                         const uint32_t* b) {
    asm volatile(
        "mma.sync.aligned.m16n8k16.row.col.f32.bf16.bf16.f32 "
        "{%0,%1,%2,%3}, {%4,%5,%6,%7}, {%8,%9}, {%0,%1,%2,%3};"
        : "+f"(c[0]), "+f"(c[1]), "+f"(c[2]), "+f"(c[3])
        : "r"(a[0]), "r"(a[1]), "r"(a[2]), "r"(a[3]), "r"(b[0]), "r"(b[1]));
}
#define CP_ASYNC(dst, src) \
    asm volatile("cp.async.cg.shared.global [%0], [%1], 16;" \
                 :: "r"(dst), "l"(src) : "memory")
#define CP_COMMIT() asm volatile("cp.async.commit_group;" ::: "memory")
#define CP_WAIT(n)  asm volatile("cp.async.wait_group %0;" :: "n"(n) : "memory")

__device__ __forceinline__ void split1(float v, bf16& h, bf16& l) {
    h = __float2bfloat16(v);
    l = __float2bfloat16(v - __bfloat162float(h));
}

// ---------------------------------------------------------------------------
// fp32 -> (hi, lo) bf16 splits
// ---------------------------------------------------------------------------
__global__ __launch_bounds__(256) void split_kernel(
    const float* __restrict__ src, bf16* __restrict__ hi,
    bf16* __restrict__ lo, int n4)
{
    int i = blockIdx.x * blockDim.x + threadIdx.x;
    if (i >= n4) return;
    float4 v = ((const float4*)src)[i];
    float a[4] = {v.x, v.y, v.z, v.w};
    bf16 h[4], l[4];
#pragma unroll
    for (int j = 0; j < 4; j++) split1(a[j], h[j], l[j]);
    ((__nv_bfloat162*)hi)[2 * i + 0] = __halves2bfloat162(h[0], h[1]);
    ((__nv_bfloat162*)hi)[2 * i + 1] = __halves2bfloat162(h[2], h[3]);
    ((__nv_bfloat162*)lo)[2 * i + 0] = __halves2bfloat162(l[0], l[1]);
    ((__nv_bfloat162*)lo)[2 * i + 1] = __halves2bfloat162(l[2], l[3]);
}

// all 4 weight matrices in one launch; blockIdx.y selects the matrix
__global__ __launch_bounds__(256) void split_w4_kernel(
    const float* __restrict__ w0, const float* __restrict__ w1,
    const float* __restrict__ w2, const float* __restrict__ w3,
    bf16* __restrict__ hiBase, bf16* __restrict__ loBase, int n4)
{
    const int j = blockIdx.y;
    const float* src = (j == 0) ? w0 : (j == 1) ? w1 : (j == 2) ? w2 : w3;
    bf16* hi = hiBase + (size_t)j * EMB * EMB;
    bf16* lo = loBase + (size_t)j * EMB * EMB;
    int i = blockIdx.x * blockDim.x + threadIdx.x;
    if (i >= n4) return;
    float4 v = ((const float4*)src)[i];
    float a[4] = {v.x, v.y, v.z, v.w};
    bf16 h[4], l[4];
#pragma unroll
    for (int k = 0; k < 4; k++) split1(a[k], h[k], l[k]);
    ((__nv_bfloat162*)hi)[2 * i + 0] = __halves2bfloat162(h[0], h[1]);
    ((__nv_bfloat162*)hi)[2 * i + 1] = __halves2bfloat162(h[2], h[3]);
    ((__nv_bfloat162*)lo)[2 * i + 0] = __halves2bfloat162(l[0], l[1]);
    ((__nv_bfloat162*)lo)[2 * i + 1] = __halves2bfloat162(l[2], l[3]);
}

// ---------------------------------------------------------------------------
// Shared GEMM mainloop: 128x128 CTA tile, BK=32, 2-stage cp.async pipeline,
// single __syncthreads per iteration, 3-term hi/lo bf16 mma.
// ---------------------------------------------------------------------------
#define BK        32
#define SSTR      40
#define TILE_B    (128 * SSTR * 2)          // 10240 B
#define STAGE_B   (4 * TILE_B)              // 40960 B
#define GEMM_SMEM (2 * STAGE_B)             // 81920 B
#define NSTEP     (EMB / BK)                // 24

__device__ __forceinline__ void gemm_mainloop(
    const bf16* __restrict__ Ah, const bf16* __restrict__ Al,
    const bf16* __restrict__ Bh, const bf16* __restrict__ Bl,
    int m0, int n0, uint32_t u0, int tid, float (&acc)[2][8][4])
{
    const int lane   = tid & 31;
    const int wid    = tid >> 5;
    const int warp_m = (wid & 3) << 5;
    const int warp_n = (wid >> 2) << 6;

    const int a_r = lane & 15;
    const int a_k = (lane >> 4) << 3;
    const int b_n = (lane & 7) + ((lane >> 4) << 3);
    const int b_k = ((lane >> 3) & 1) << 3;

    const int f_row = tid >> 2;
    const int f_c16 = tid & 3;

#define FILL(stage, k0) do {                                                   \
        const uint32_t sb = u0 + (stage) * STAGE_B;                            \
        _Pragma("unroll")                                                      \
        for (int t = 0; t < 4; t++) {                                          \
            const bf16* sp = (t == 0) ? Ah : (t == 1) ? Al : (t == 2) ? Bh : Bl;\
            const int rb = (t < 2) ? m0 : n0;                                  \
            _Pragma("unroll")                                                  \
            for (int sub = 0; sub < 2; sub++) {                                \
                const int row = f_row + sub * 64;                              \
                CP_ASYNC(sb + t * TILE_B + row * (SSTR * 2) + f_c16 * 16,      \
                         sp + (size_t)(rb + row) * EMB + (k0) + f_c16 * 8);    \
            }                                                                  \
        }                                                                      \
        CP_COMMIT();                                                           \
    } while (0)

    FILL(0, 0);

    for (int s = 0; s < NSTEP; s++) {
        CP_WAIT(0);
        __syncthreads();
        if (s + 1 < NSTEP) FILL((s + 1) & 1, (s + 1) * BK);

        const uint32_t sb  = u0 + (s & 1) * STAGE_B;
        const uint32_t uAh = sb;
        const uint32_t uAl = sb + TILE_B;
        const uint32_t uBh = sb + 2 * TILE_B;
        const uint32_t uBl = sb + 3 * TILE_B;

#pragma unroll
        for (int ks = 0; ks < 2; ks++) {
            const int kk = ks << 4;
            uint32_t aH[2][4], aL[2][4];
#pragma unroll
            for (int mi = 0; mi < 2; mi++) {
                const uint32_t off =
                    (uint32_t)((warp_m + mi * 16 + a_r) * SSTR + kk + a_k) * 2;
                ldsm4(aH[mi], uAh + off);
                ldsm4(aL[mi], uAl + off);
            }
#pragma unroll
            for (int np = 0; np < 4; np++) {
                uint32_t bH[4], bL[4];
                const uint32_t off =
                    (uint32_t)((warp_n + np * 16 + b_n) * SSTR + kk + b_k) * 2;
                ldsm4(bH, uBh + off);
                ldsm4(bL, uBl + off);
#pragma unroll
                for (int mi = 0; mi < 2; mi++) {
#pragma unroll
                    for (int ss = 0; ss < 2; ss++) {
                        float* c = acc[mi][np * 2 + ss];
                        mma_bf16(c, aH[mi], bH + 2 * ss);
                        mma_bf16(c, aL[mi], bH + 2 * ss);
                        mma_bf16(c, aH[mi], bL + 2 * ss);
                    }
                }
            }
        }
        __syncthreads();   // compute done before next FILL overwrites this stage
    }
#undef FILL
}

// Fused QKV projection: blockIdx.z selects {Q, K, V}
__global__ __launch_bounds__(256, 2) void gemm_qkv(
    const bf16* __restrict__ Xh, const bf16* __restrict__ Xl,
    const bf16* __restrict__ WhB, const bf16* __restrict__ WlB,
    const float* __restrict__ bq, const float* __restrict__ bk,
    const float* __restrict__ bv,
    bf16* __restrict__ qh, bf16* __restrict__ ql,
    bf16* __restrict__ kh, bf16* __restrict__ kl,
    bf16* __restrict__ vth, bf16* __restrict__ vtl)
{
    extern __shared__ char dsm[];
    const uint32_t u0 = smem_u32(dsm);
    const int tid  = threadIdx.x;
    const int lane = tid & 31;
    const int wid  = tid >> 5;
    const int m0 = blockIdx.y << 7;
    const int n0 = blockIdx.x << 7;
    const int z  = blockIdx.z;

    const size_t WSZ = (size_t)EMB * EMB;
    const bf16* Bh = WhB + (size_t)z * WSZ;
    const bf16* Bl = WlB + (size_t)z * WSZ;
    const float* bias = (z == 0) ? bq : (z == 1) ? bk : bv;
    const float scale = (z == 0) ? 0.125f : 1.0f;
    bf16* oh = (z == 0) ? qh : (z == 1) ? kh : vth;
    bf16* ol = (z == 0) ? ql : (z == 1) ? kl : vtl;

    float acc[2][8][4];
#pragma unroll
    for (int mi = 0; mi < 2; mi++)
#pragma unroll
        for (int ni = 0; ni < 8; ni++)
#pragma unroll
            for (int q = 0; q < 4; q++) acc[mi][ni][q] = 0.f;

    gemm_mainloop(Xh, Xl, Bh, Bl, m0, n0, u0, tid, acc);

    const int warp_m = (wid & 3) << 5;
    const int warp_n = (wid >> 2) << 6;
#pragma unroll
    for (int mi = 0; mi < 2; mi++) {
#pragma unroll
        for (int rr = 0; rr < 2; rr++) {
            const int m = m0 + warp_m + mi * 16 + rr * 8 + (lane >> 2);
            const int irow = m >> 8;
            const int ccol = m & 255;
#pragma unroll
            for (int ni = 0; ni < 8; ni++) {
                const int col = n0 + warp_n + ni * 8 + ((lane & 3) << 1);
                const float2 bv2 = *(const float2*)&bias[col];
                const float v0 = (acc[mi][ni][rr * 2 + 0] + bv2.x) * scale;
                const float v1 = (acc[mi][ni][rr * 2 + 1] + bv2.y) * scale;
                bf16 h0, l0, h1, l1;
                split1(v0, h0, l0); split1(v1, h1, l1);
                const int hh = col >> 6;
                const int dd = col & 63;
                if (z < 2) {
                    const size_t o = (((size_t)ccol * NH + hh) * RR + irow) * DKD + dd;
                    *(__nv_bfloat162*)&oh[o] = __halves2bfloat162(h0, h1);
                    *(__nv_bfloat162*)&ol[o] = __halves2bfloat162(l0, l1);
                } else {
                    const size_t o = (((size_t)ccol * NH + hh) * DKD + dd) * RR + irow;
                    oh[o] = h0; oh[o + RR] = h1;
                    ol[o] = l0; ol[o + RR] = l1;
                }
            }
        }
    }
}

// Output projection: fp32 out
__global__ __launch_bounds__(256, 2) void gemm_o(
    const bf16* __restrict__ Ch, const bf16* __restrict__ Cl,
    const bf16* __restrict__ Wh, const bf16* __restrict__ Wl,
    const float* __restrict__ bias, float* __restrict__ out)
{
    extern __shared__ char dsm[];
    const uint32_t u0 = smem_u32(dsm);
    const int tid  = threadIdx.x;
    const int lane = tid & 31;
    const int wid  = tid >> 5;
    const int m0 = blockIdx.y << 7;
    const int n0 = blockIdx.x << 7;

    float acc[2][8][4];
#pragma unroll
    for (int mi = 0; mi < 2; mi++)
#pragma unroll
        for (int ni = 0; ni < 8; ni++)
#pragma unroll
            for (int q = 0; q < 4; q++) acc[mi][ni][q] = 0.f;

    gemm_mainloop(Ch, Cl, Wh, Wl, m0, n0, u0, tid, acc);

    const int warp_m = (wid & 3) << 5;
    const int warp_n = (wid >> 2) << 6;
#pragma unroll
    for (int mi = 0; mi < 2; mi++) {
#pragma unroll
        for (int rr = 0; rr < 2; rr++) {
            const int m = m0 + warp_m + mi * 16 + rr * 8 + (lane >> 2);
#pragma unroll
            for (int ni = 0; ni < 8; ni++) {
                const int col = n0 + warp_n + ni * 8 + ((lane & 3) << 1);
                const float2 bv2 = *(const float2*)&bias[col];
                *(float2*)&out[(size_t)m * EMB + col] =
                    make_float2(acc[mi][ni][rr * 2 + 0] + bv2.x,
                                acc[mi][ni][rr * 2 + 1] + bv2.y);
            }
        }
    }
}

// ---------------------------------------------------------------------------
// Tensor-core attention, register-resident softmax, 110.7KB smem (2 CTA/SM).
// ---------------------------------------------------------------------------
#define QS 72     // 64-wide bf16 tiles, stride 144 B
#define PS 136    // 128-wide bf16 tiles, stride 272 B

#define AOFF_QH  0
#define AOFF_QL  (AOFF_QH + 128 * QS * 2)    // 18432
#define AOFF_KH  (AOFF_QL + 128 * QS * 2)    // 36864
#define AOFF_KL  (AOFF_KH + 128 * QS * 2)    // 55296
#define AOFF_VH  (AOFF_KL + 128 * QS * 2)    // 73728
#define AOFF_VL  (AOFF_VH + 64 * PS * 2)     // 91136
#define AOFF_ST  (AOFF_VL + 64 * PS * 2)     // 108544 (sMax 256f, sSum 256f)
#define AOFF_MK  (AOFF_ST + 2048)            // 110592
#define ATTN_SMEM (AOFF_MK + 128)            // 110720
#define AOFF_PH  0                            // P overlays Q/K region after use
#define AOFF_PL  (AOFF_PH + 128 * PS * 2)    // 34816 (PH+PL = 69632 < 73728)

__global__ __launch_bounds__(256, 2) void attn_mma(
    const bf16* __restrict__ qh, const bf16* __restrict__ ql,
    const bf16* __restrict__ kh, const bf16* __restrict__ kl,
    const bf16* __restrict__ vth, const bf16* __restrict__ vtl,
    const unsigned char* __restrict__ mask,
    float* __restrict__ probs, int write_probs)
{
    extern __shared__ char dsm[];
    const uint32_t u0 = smem_u32(dsm);
    float* sMax = (float*)(dsm + AOFF_ST);
    float* sSum = sMax + 256;
    unsigned char* sMask = (unsigned char*)(dsm + AOFF_MK);

    const int c   = blockIdx.x;
    const int h   = blockIdx.y;
    const int tid = threadIdx.x;
    const int lane = tid & 31;
    const int wid  = tid >> 5;
    const size_t base = (((size_t)c * NH + h) * RR) * DKD;

    // ---- load tiles via cp.async ----
    {
        const int row_q = tid >> 1;
        const int c16_q = tid & 1;
        const bf16* srcs[4] = {qh, ql, kh, kl};
        const uint32_t dsts[4] = {u0 + AOFF_QH, u0 + AOFF_QL,
                                  u0 + AOFF_KH, u0 + AOFF_KL};
#pragma unroll
        for (int t = 0; t < 4; t++) {
#pragma unroll
            for (int sub = 0; sub < 4; sub++) {
                const int cid = sub * 2 + c16_q;
                CP_ASYNC(dsts[t] + row_q * (QS * 2) + cid * 16,
                         srcs[t] + base + (size_t)row_q * DKD + cid * 8);
            }
        }
        const int row_v = tid >> 2;
        const int c4_v  = tid & 3;
#pragma unroll
        for (int sub = 0; sub < 4; sub++) {
            const int cid = sub * 4 + c4_v;
            CP_ASYNC(u0 + AOFF_VH + row_v * (PS * 2) + cid * 16,
                     vth + base + (size_t)row_v * RR + cid * 8);
            CP_ASYNC(u0 + AOFF_VL + row_v * (PS * 2) + cid * 16,
                     vtl + base + (size_t)row_v * RR + cid * 8);
        }
        CP_COMMIT();
        if (tid < 128) sMask[tid] = mask[(size_t)tid * CC + c];
        CP_WAIT(0);
    }
    __syncthreads();

    const int a_r = lane & 15;
    const int a_k = (lane >> 4) << 3;
    const int b_n = (lane & 7) + ((lane >> 4) << 3);
    const int b_k = ((lane >> 3) & 1) << 3;
    const int warp_m = (wid & 3) << 5;
    const int half   = wid >> 2;            // which n-half of S this warp owns
    const int warp_n = half << 6;

    // ---- S = Q K^T (M=128, N=128, K=64), scores stay in registers ----
    float acc[2][8][4];
#pragma unroll
    for (int mi = 0; mi < 2; mi++)
#pragma unroll
        for (int ni = 0; ni < 8; ni++)
#pragma unroll
            for (int q = 0; q < 4; q++) acc[mi][ni][q] = 0.f;

#pragma unroll
    for (int ks = 0; ks < 4; ks++) {
        const int kk = ks << 4;
        uint32_t aH[2][4], aL[2][4];
#pragma unroll
        for (int mi = 0; mi < 2; mi++) {
            const uint32_t off =
                (uint32_t)((warp_m + mi * 16 + a_r) * QS + kk + a_k) * 2;
            ldsm4(aH[mi], u0 + AOFF_QH + off);
            ldsm4(aL[mi], u0 + AOFF_QL + off);
        }
#pragma unroll
        for (int np = 0; np < 4; np++) {
            uint32_t bH[4], bL[4];
            const uint32_t off =
                (uint32_t)((warp_n + np * 16 + b_n) * QS + kk + b_k) * 2;
            ldsm4(bH, u0 + AOFF_KH + off);
            ldsm4(bL, u0 + AOFF_KL + off);
#pragma unroll
            for (int mi = 0; mi < 2; mi++) {
#pragma unroll
                for (int ss = 0; ss < 2; ss++) {
                    float* cp = acc[mi][np * 2 + ss];
                    mma_bf16(cp, aH[mi], bH + 2 * ss);
                    mma_bf16(cp, aL[mi], bH + 2 * ss);
                    mma_bf16(cp, aH[mi], bL + 2 * ss);
                }
            }
        }
    }

    // ---- mask (col-only) ----
#pragma unroll
    for (int ni = 0; ni < 8; ni++) {
        const int c0 = warp_n + ni * 8 + ((lane & 3) << 1);
        if (sMask[c0]) {
            acc[0][ni][0] = -10000.f; acc[0][ni][2] = -10000.f;
            acc[1][ni][0] = -10000.f; acc[1][ni][2] = -10000.f;
        }
        if (sMask[c0 + 1]) {
            acc[0][ni][1] = -10000.f; acc[0][ni][3] = -10000.f;
            acc[1][ni][1] = -10000.f; acc[1][ni][3] = -10000.f;
        }
    }

    // ---- row max: 16 vals/thread -> 4-lane bfly -> cross-half via smem ----
#pragma unroll
    for (int mi = 0; mi < 2; mi++)
#pragma unroll
        for (int rr = 0; rr < 2; rr++) {
            float mx = -1e30f;
#pragma unroll
            for (int ni = 0; ni < 8; ni++) {
                mx = fmaxf(mx, acc[mi][ni][rr * 2 + 0]);
                mx = fmaxf(mx, acc[mi][ni][rr * 2 + 1]);
            }
            mx = fmaxf(mx, __shfl_xor_sync(0xFFFFFFFFu, mx, 1));
            mx = fmaxf(mx, __shfl_xor_sync(0xFFFFFFFFu, mx, 2));
            const int row = warp_m + mi * 16 + rr * 8 + (lane >> 2);
            if ((lane & 3) == 0) sMax[half * 128 + row] = mx;
        }
    __syncthreads();

    // ---- exp + row sum ----
#pragma unroll
    for (int mi = 0; mi < 2; mi++)
#pragma unroll
        for (int rr = 0; rr < 2; rr++) {
            const int row = warp_m + mi * 16 + rr * 8 + (lane >> 2);
            const float m = fmaxf(sMax[row], sMax[128 + row]);
            float s = 0.f;
#pragma unroll
            for (int ni = 0; ni < 8; ni++) {
                float e0 = __expf(acc[mi][ni][rr * 2 + 0] - m);
                float e1 = __expf(acc[mi][ni][rr * 2 + 1] - m);
                acc[mi][ni][rr * 2 + 0] = e0;
                acc[mi][ni][rr * 2 + 1] = e1;
                s += e0 + e1;
            }
            s += __shfl_xor_sync(0xFFFFFFFFu, s, 1);
            s += __shfl_xor_sync(0xFFFFFFFFu, s, 2);
            if ((lane & 3) == 0) sSum[half * 128 + row] = s;
        }
    __syncthreads();

    // ---- normalize, write probs, split P to bf16 hi/lo (overlay Q/K) ----
    {
        bf16* Ph = (bf16*)(dsm + AOFF_PH);
        bf16* Pl = (bf16*)(dsm + AOFF_PL);
        float* pb = probs + (((size_t)h * CC + c) * RR) * RR;
#pragma unroll
        for (int mi = 0; mi < 2; mi++)
#pragma unroll
            for (int rr = 0; rr < 2; rr++) {
                const int row = warp_m + mi * 16 + rr * 8 + (lane >> 2);
                const float inv = 1.f / (sSum[row] + sSum[128 + row]);
#pragma unroll
                for (int ni = 0; ni < 8; ni++) {
                    const int col = warp_n + ni * 8 + ((lane & 3) << 1);
                    const float p0 = acc[mi][ni][rr * 2 + 0] * inv;
                    const float p1 = acc[mi][ni][rr * 2 + 1] * inv;
                    if (write_probs)
                        *(float2*)&pb[(size_t)row * RR + col] = make_float2(p0, p1);
                    bf16 h0, l0, h1, l1;
                    split1(p0, h0, l0); split1(p1, h1, l1);
                    *(__nv_bfloat162*)&Ph[row * PS + col] = __halves2bfloat162(h0, h1);
                    *(__nv_bfloat162*)&Pl[row * PS + col] = __halves2bfloat162(l0, l1);
                }
            }
    }
    __syncthreads();

    // ---- ctx = P V (M=128, N=64, K=128) ----
    {
        const int warp_nd = half << 5;
        float acc2[2][4][4];
#pragma unroll
        for (int mi = 0; mi < 2; mi++)
#pragma unroll
            for (int ni = 0; ni < 4; ni++)
#pragma unroll
                for (int q = 0; q < 4; q++) acc2[mi][ni][q] = 0.f;

#pragma unroll
        for (int ks = 0; ks < 8; ks++) {
            const int kk = ks << 4;
            uint32_t aH[2][4], aL[2][4];
#pragma unroll
            for (int mi = 0; mi < 2; mi++) {
                const uint32_t off =
                    (uint32_t)((warp_m + mi * 16 + a_r) * PS + kk + a_k) * 2;
                ldsm4(aH[mi], u0 + AOFF_PH + off);
                ldsm4(aL[mi], u0 + AOFF_PL + off);
            }
#pragma unroll
            for (int np = 0; np < 2; np++) {
                uint32_t bH[4], bL[4];
                const uint32_t off =
                    (uint32_t)((warp_nd + np * 16 + b_n) * PS + kk + b_k) * 2;
                ldsm4(bH, u0 + AOFF_VH + off);
                ldsm4(bL, u0 + AOFF_VL + off);
#pragma unroll
                for (int mi = 0; mi < 2; mi++) {
#pragma unroll
                    for (int ss = 0; ss < 2; ss++) {
                        float* cp = acc2[mi][np * 2 + ss];
                        mma_bf16(cp, aH[mi], bH + 2 * ss);
                        mma_bf16(cp, aH[mi], bL + 2 * ss);
                        mma_bf16(cp, aL[mi], bH + 2 * ss);
                    }
                }
            }
        }
#pragma unroll
        for (int mi = 0; mi < 2; mi++) {
#pragma unroll
            for (int rr = 0; rr < 2; rr++) {
                const int i = warp_m + mi * 16 + rr * 8 + (lane >> 2);
                const size_t tok = (size_t)i * CC + c;
#pragma unroll
                for (int ni = 0; ni < 4; ni++) {
                    const int d = warp_nd + ni * 8 + ((lane & 3) << 1);
                    bf16 h0, l0, h1, l1;
                    split1(acc2[mi][ni][rr * 2 + 0], h0, l0);
                    split1(acc2[mi][ni][rr * 2 + 1], h1, l1);
                    const size_t o = tok * EMB + h * DKD + d;
                    *(__nv_bfloat162*)&g_Ch[o] = __halves2bfloat162(h0, h1);
                    *(__nv_bfloat162*)&g_Cl[o] = __halves2bfloat162(l0, l1);
                }
            }
        }
    }
}

// ---------------------------------------------------------------------------
extern "C" void kernel_launch(void* const* d_in, const int* in_sizes, int n_in,
                              void* d_out, int out_size)
{
    const float*         x    = (const float*)d_in[0];
    const unsigned char* mask = (const unsigned char*)d_in[1];
    const float* Wq = (const float*)d_in[2];
    const float* bq = (const float*)d_in[3];
    const float* Wk = (const float*)d_in[4];
    const float* bk = (const float*)d_in[5];
    const float* Wv = (const float*)d_in[6];
    const float* bv = (const float*)d_in[7];
    const float* Wo = (const float*)d_in[8];
    const float* bo = (const float*)d_in[9];
    float* out = (float*)d_out;

    const long long OUT_E   = (long long)NT * EMB;
    const long long PROBS_E = (long long)NH * CC * RR * RR;

    float* probs = nullptr;
    int write_probs = 0;
    int do_output = 1;
    if ((long long)out_size >= OUT_E + PROBS_E) {
        probs = out + OUT_E;
        write_probs = 1;
    } else if ((long long)out_size == PROBS_E) {
        probs = out;
        write_probs = 1;
        do_output = 0;
    }

    void *xh, *xl, *wh, *wl, *qh_, *ql_, *kh_, *kl_, *vh_, *vl_, *ch, *cl;
    cudaGetSymbolAddress(&xh, g_Xh);  cudaGetSymbolAddress(&xl, g_Xl);
    cudaGetSymbolAddress(&wh, g_Wh);  cudaGetSymbolAddress(&wl, g_Wl);
    cudaGetSymbolAddress(&qh_, g_Qh); cudaGetSymbolAddress(&ql_, g_Ql);
    cudaGetSymbolAddress(&kh_, g_Kh); cudaGetSymbolAddress(&kl_, g_Kl);
    cudaGetSymbolAddress(&vh_, g_Vth); cudaGetSymbolAddress(&vl_, g_Vtl);
    cudaGetSymbolAddress(&ch, g_Ch);  cudaGetSymbolAddress(&cl, g_Cl);

    bf16* Xh = (bf16*)xh; bf16* Xl = (bf16*)xl;
    bf16* Wh = (bf16*)wh; bf16* Wl = (bf16*)wl;
    const size_t WSZ = (size_t)EMB * EMB;

    static int attr_set = 0;
    if (!attr_set) {
        cudaFuncSetAttribute(gemm_qkv,
                             cudaFuncAttributeMaxDynamicSharedMemorySize, GEMM_SMEM);
        cudaFuncSetAttribute(gemm_o,
                             cudaFuncAttributeMaxDynamicSharedMemorySize, GEMM_SMEM);
        cudaFuncSetAttribute(attn_mma,
                             cudaFuncAttributeMaxDynamicSharedMemorySize, ATTN_SMEM);
        attr_set = 1;
    }

    split_kernel<<<(NT * EMB / 4 + 255) / 256, 256>>>(x, Xh, Xl, NT * EMB / 4);
    split_w4_kernel<<<dim3((unsigned)((WSZ / 4 + 255) / 256), 4), 256>>>(
        Wq, Wk, Wv, Wo, Wh, Wl, (int)(WSZ / 4));

    gemm_qkv<<<dim3(6, 256, 3), 256, GEMM_SMEM>>>(
        Xh, Xl, Wh, Wl, bq, bk, bv,
        (bf16*)qh_, (bf16*)ql_, (bf16*)kh_, (bf16*)kl_, (bf16*)vh_, (bf16*)vl_);

    attn_mma<<<dim3(CC, NH), 256, ATTN_SMEM>>>(
        (const bf16*)qh_, (const bf16*)ql_, (const bf16*)kh_, (const bf16*)kl_,
        (const bf16*)vh_, (const bf16*)vl_, mask, probs, write_probs);

    if (do_output)
        gemm_o<<<dim3(6, 256), 256, GEMM_SMEM>>>(
            (const bf16*)ch, (const bf16*)cl, Wh + 3 * WSZ, Wl + 3 * WSZ, bo, out);
}

// round 11
// speedup vs baseline: 3.4959x; 1.3084x over previous
#include <cuda_runtime.h>
#include <cuda_bf16.h>
#include <cstdint>

#define RR   128
#define CC   256
#define EMB  768
#define NH   12
#define DKD  64
#define NT   (RR * CC)          // 32768 tokens

typedef __nv_bfloat16 bf16;

// ---------------- scratch (__device__ globals, allocation-free) -------------
__device__ bf16 g_Xh[(size_t)NT * EMB];
__device__ bf16 g_Xl[(size_t)NT * EMB];
__device__ bf16 g_Wh[4][(size_t)EMB * EMB];
__device__ bf16 g_Wl[4][(size_t)EMB * EMB];
__device__ bf16 g_Qh[(size_t)CC * NH * RR * DKD];   // [c][h][i][d]
__device__ bf16 g_Ql[(size_t)CC * NH * RR * DKD];
__device__ bf16 g_Kh[(size_t)CC * NH * RR * DKD];
__device__ bf16 g_Kl[(size_t)CC * NH * RR * DKD];
__device__ bf16 g_Vh[(size_t)CC * NH * RR * DKD];   // [c][h][i][d] (row-major now)
__device__ bf16 g_Vl[(size_t)CC * NH * RR * DKD];
__device__ bf16 g_Ch[(size_t)NT * EMB];             // ctx hi/lo [t][e]
__device__ bf16 g_Cl[(size_t)NT * EMB];

// ---------------------------- helpers --------------------------------------
__device__ __forceinline__ uint32_t smem_u32(const void* p) {
    uint32_t a;
    asm("{ .reg .u64 t; cvta.to.shared.u64 t, %1; cvt.u32.u64 %0, t; }"
        : "=r"(a) : "l"(p));
    return a;
}
__device__ __forceinline__ void ldsm4(uint32_t* r, uint32_t addr) {
    asm volatile("ldmatrix.sync.aligned.m8n8.x4.shared.b16 {%0,%1,%2,%3}, [%4];"
                 : "=r"(r[0]), "=r"(r[1]), "=r"(r[2]), "=r"(r[3]) : "r"(addr));
}
__device__ __forceinline__ void ldsm4t(uint32_t* r, uint32_t addr) {
    asm volatile("ldmatrix.sync.aligned.m8n8.x4.trans.shared.b16 {%0,%1,%2,%3}, [%4];"
                 : "=r"(r[0]), "=r"(r[1]), "=r"(r[2]), "=r"(r[3]) : "r"(addr));
}
__device__ __forceinline__ void mma_bf16(float* c, const uint32_t* a,
                                         const uint32_t* b) {
    asm volatile(
        "mma.sync.aligned.m16n8k16.row.col.f32.bf16.bf16.f32 "
        "{%0,%1,%2,%3}, {%4,%5,%6,%7}, {%8,%9}, {%0,%1,%2,%3};"
        : "+f"(c[0]), "+f"(c[1]), "+f"(c[2]), "+f"(c[3])
        : "r"(a[0]), "r"(a[1]), "r"(a[2]), "r"(a[3]), "r"(b[0]), "r"(b[1]));
}
#define CP_ASYNC(dst, src) \
    asm volatile("cp.async.cg.shared.global [%0], [%1], 16;" \
                 :: "r"(dst), "l"(src) : "memory")
#define CP_COMMIT() asm volatile("cp.async.commit_group;" ::: "memory")
#define CP_WAIT(n)  asm volatile("cp.async.wait_group %0;" :: "n"(n) : "memory")

__device__ __forceinline__ void split1(float v, bf16& h, bf16& l) {
    h = __float2bfloat16(v);
    l = __float2bfloat16(v - __bfloat162float(h));
}

// ---------------------------------------------------------------------------
// fp32 -> (hi, lo) bf16 splits
// ---------------------------------------------------------------------------
__global__ __launch_bounds__(256) void split_kernel(
    const float* __restrict__ src, bf16* __restrict__ hi,
    bf16* __restrict__ lo, int n4)
{
    int i = blockIdx.x * blockDim.x + threadIdx.x;
    if (i >= n4) return;
    float4 v = ((const float4*)src)[i];
    float a[4] = {v.x, v.y, v.z, v.w};
    bf16 h[4], l[4];
#pragma unroll
    for (int j = 0; j < 4; j++) split1(a[j], h[j], l[j]);
    ((__nv_bfloat162*)hi)[2 * i + 0] = __halves2bfloat162(h[0], h[1]);
    ((__nv_bfloat162*)hi)[2 * i + 1] = __halves2bfloat162(h[2], h[3]);
    ((__nv_bfloat162*)lo)[2 * i + 0] = __halves2bfloat162(l[0], l[1]);
    ((__nv_bfloat162*)lo)[2 * i + 1] = __halves2bfloat162(l[2], l[3]);
}

__global__ __launch_bounds__(256) void split_w4_kernel(
    const float* __restrict__ w0, const float* __restrict__ w1,
    const float* __restrict__ w2, const float* __restrict__ w3,
    bf16* __restrict__ hiBase, bf16* __restrict__ loBase, int n4)
{
    const int j = blockIdx.y;
    const float* src = (j == 0) ? w0 : (j == 1) ? w1 : (j == 2) ? w2 : w3;
    bf16* hi = hiBase + (size_t)j * EMB * EMB;
    bf16* lo = loBase + (size_t)j * EMB * EMB;
    int i = blockIdx.x * blockDim.x + threadIdx.x;
    if (i >= n4) return;
    float4 v = ((const float4*)src)[i];
    float a[4] = {v.x, v.y, v.z, v.w};
    bf16 h[4], l[4];
#pragma unroll
    for (int k = 0; k < 4; k++) split1(a[k], h[k], l[k]);
    ((__nv_bfloat162*)hi)[2 * i + 0] = __halves2bfloat162(h[0], h[1]);
    ((__nv_bfloat162*)hi)[2 * i + 1] = __halves2bfloat162(h[2], h[3]);
    ((__nv_bfloat162*)lo)[2 * i + 0] = __halves2bfloat162(l[0], l[1]);
    ((__nv_bfloat162*)lo)[2 * i + 1] = __halves2bfloat162(l[2], l[3]);
}

// ---------------------------------------------------------------------------
// Shared GEMM mainloop: 128x128 CTA tile, BK=32, 2-stage cp.async pipeline,
// ONE __syncthreads per iteration, 3-term hi/lo bf16 mma.
// ---------------------------------------------------------------------------
#define BK        32
#define SSTR      40
#define TILE_B    (128 * SSTR * 2)          // 10240 B
#define STAGE_B   (4 * TILE_B)              // 40960 B
#define GEMM_SMEM (2 * STAGE_B)             // 81920 B
#define NSTEP     (EMB / BK)                // 24
#define ESTR      136                        // bf16 epilogue smem stride
#define ESTR4     132                        // fp32 epilogue smem stride

__device__ __forceinline__ void gemm_mainloop(
    const bf16* __restrict__ Ah, const bf16* __restrict__ Al,
    const bf16* __restrict__ Bh, const bf16* __restrict__ Bl,
    int m0, int n0, uint32_t u0, int tid, float (&acc)[2][8][4])
{
    const int lane   = tid & 31;
    const int wid    = tid >> 5;
    const int warp_m = (wid & 3) << 5;
    const int warp_n = (wid >> 2) << 6;

    const int a_r = lane & 15;
    const int a_k = (lane >> 4) << 3;
    const int b_n = (lane & 7) + ((lane >> 4) << 3);
    const int b_k = ((lane >> 3) & 1) << 3;

    const int f_row = tid >> 2;
    const int f_c16 = tid & 3;

#define FILL(stage, k0) do {                                                   \
        const uint32_t sb = u0 + (stage) * STAGE_B;                            \
        _Pragma("unroll")                                                      \
        for (int t = 0; t < 4; t++) {                                          \
            const bf16* sp = (t == 0) ? Ah : (t == 1) ? Al : (t == 2) ? Bh : Bl;\
            const int rb = (t < 2) ? m0 : n0;                                  \
            _Pragma("unroll")                                                  \
            for (int sub = 0; sub < 2; sub++) {                                \
                const int row = f_row + sub * 64;                              \
                CP_ASYNC(sb + t * TILE_B + row * (SSTR * 2) + f_c16 * 16,      \
                         sp + (size_t)(rb + row) * EMB + (k0) + f_c16 * 8);    \
            }                                                                  \
        }                                                                      \
        CP_COMMIT();                                                           \
    } while (0)

    FILL(0, 0);

    for (int s = 0; s < NSTEP; s++) {
        CP_WAIT(0);
        __syncthreads();               // copies visible + prev compute done
        if (s + 1 < NSTEP) FILL((s + 1) & 1, (s + 1) * BK);

        const uint32_t sb  = u0 + (s & 1) * STAGE_B;
        const uint32_t uAh = sb;
        const uint32_t uAl = sb + TILE_B;
        const uint32_t uBh = sb + 2 * TILE_B;
        const uint32_t uBl = sb + 3 * TILE_B;

#pragma unroll
        for (int ks = 0; ks < 2; ks++) {
            const int kk = ks << 4;
            uint32_t aH[2][4], aL[2][4];
#pragma unroll
            for (int mi = 0; mi < 2; mi++) {
                const uint32_t off =
                    (uint32_t)((warp_m + mi * 16 + a_r) * SSTR + kk + a_k) * 2;
                ldsm4(aH[mi], uAh + off);
                ldsm4(aL[mi], uAl + off);
            }
#pragma unroll
            for (int np = 0; np < 4; np++) {
                uint32_t bH[4], bL[4];
                const uint32_t off =
                    (uint32_t)((warp_n + np * 16 + b_n) * SSTR + kk + b_k) * 2;
                ldsm4(bH, uBh + off);
                ldsm4(bL, uBl + off);
#pragma unroll
                for (int mi = 0; mi < 2; mi++) {
#pragma unroll
                    for (int ss = 0; ss < 2; ss++) {
                        float* c = acc[mi][np * 2 + ss];
                        mma_bf16(c, aH[mi], bH + 2 * ss);
                        mma_bf16(c, aL[mi], bH + 2 * ss);
                        mma_bf16(c, aH[mi], bL + 2 * ss);
                    }
                }
            }
        }
    }
    __syncthreads();   // mainloop smem free for epilogue staging
#undef FILL
}

// Fused QKV projection: blockIdx.z selects {Q, K, V}; all outputs [c][h][i][d]
__global__ __launch_bounds__(256, 2) void gemm_qkv(
    const bf16* __restrict__ Xh, const bf16* __restrict__ Xl,
    const bf16* __restrict__ WhB, const bf16* __restrict__ WlB,
    const float* __restrict__ bq, const float* __restrict__ bk,
    const float* __restrict__ bv,
    bf16* __restrict__ qh, bf16* __restrict__ ql,
    bf16* __restrict__ kh, bf16* __restrict__ kl,
    bf16* __restrict__ vh, bf16* __restrict__ vl)
{
    extern __shared__ char dsm[];
    const uint32_t u0 = smem_u32(dsm);
    const int tid  = threadIdx.x;
    const int lane = tid & 31;
    const int wid  = tid >> 5;
    const int m0 = blockIdx.y << 7;
    const int n0 = blockIdx.x << 7;
    const int z  = blockIdx.z;

    const size_t WSZ = (size_t)EMB * EMB;
    const bf16* Bh = WhB + (size_t)z * WSZ;
    const bf16* Bl = WlB + (size_t)z * WSZ;
    const float* bias = (z == 0) ? bq : (z == 1) ? bk : bv;
    const float scale = (z == 0) ? 0.125f : 1.0f;
    bf16* oh = (z == 0) ? qh : (z == 1) ? kh : vh;
    bf16* ol = (z == 0) ? ql : (z == 1) ? kl : vl;

    float acc[2][8][4];
#pragma unroll
    for (int mi = 0; mi < 2; mi++)
#pragma unroll
        for (int ni = 0; ni < 8; ni++)
#pragma unroll
            for (int q = 0; q < 4; q++) acc[mi][ni][q] = 0.f;

    gemm_mainloop(Xh, Xl, Bh, Bl, m0, n0, u0, tid, acc);

    // ---- stage to smem (bias + scale + split), then coalesced store ----
    bf16* Eh = (bf16*)dsm;
    bf16* El = (bf16*)(dsm + 128 * ESTR * 2);
    const int warp_m = (wid & 3) << 5;
    const int warp_n = (wid >> 2) << 6;
#pragma unroll
    for (int mi = 0; mi < 2; mi++)
#pragma unroll
        for (int rr = 0; rr < 2; rr++) {
            const int row = warp_m + mi * 16 + rr * 8 + (lane >> 2);
#pragma unroll
            for (int ni = 0; ni < 8; ni++) {
                const int col = warp_n + ni * 8 + ((lane & 3) << 1);
                const float2 bv2 = *(const float2*)&bias[n0 + col];
                const float v0 = (acc[mi][ni][rr * 2 + 0] + bv2.x) * scale;
                const float v1 = (acc[mi][ni][rr * 2 + 1] + bv2.y) * scale;
                bf16 h0, l0, h1, l1;
                split1(v0, h0, l0); split1(v1, h1, l1);
                *(__nv_bfloat162*)&Eh[row * ESTR + col] = __halves2bfloat162(h0, h1);
                *(__nv_bfloat162*)&El[row * ESTR + col] = __halves2bfloat162(l0, l1);
            }
        }
    __syncthreads();

    const int irow  = m0 >> 8;
    const int ccol0 = m0 & 255;
    const int hh0   = n0 >> 6;
#pragma unroll
    for (int p = 0; p < 16; p++) {
        const int lr = p * 32 + (tid >> 3);   // 0..511
        const int arr = lr >> 8;              // 0 hi, 1 lo
        const int r = lr & 255;
        const int ml = r >> 1;
        const int hl = r & 1;
        const bf16* src = arr ? El : Eh;
        uint4 v = *(const uint4*)&src[ml * ESTR + hl * 64 + (tid & 7) * 8];
        bf16* dst = arr ? ol : oh;
        *(uint4*)&dst[(((size_t)(ccol0 + ml) * NH + hh0 + hl) * RR + irow) * DKD
                      + (tid & 7) * 8] = v;
    }
}

// Output projection: fp32 out, staged epilogue
__global__ __launch_bounds__(256, 2) void gemm_o(
    const bf16* __restrict__ Ch, const bf16* __restrict__ Cl,
    const bf16* __restrict__ Wh, const bf16* __restrict__ Wl,
    const float* __restrict__ bias, float* __restrict__ out)
{
    extern __shared__ char dsm[];
    const uint32_t u0 = smem_u32(dsm);
    const int tid  = threadIdx.x;
    const int lane = tid & 31;
    const int wid  = tid >> 5;
    const int m0 = blockIdx.y << 7;
    const int n0 = blockIdx.x << 7;

    float acc[2][8][4];
#pragma unroll
    for (int mi = 0; mi < 2; mi++)
#pragma unroll
        for (int ni = 0; ni < 8; ni++)
#pragma unroll
            for (int q = 0; q < 4; q++) acc[mi][ni][q] = 0.f;

    gemm_mainloop(Ch, Cl, Wh, Wl, m0, n0, u0, tid, acc);

    float* Ef = (float*)dsm;
    const int warp_m = (wid & 3) << 5;
    const int warp_n = (wid >> 2) << 6;
#pragma unroll
    for (int mi = 0; mi < 2; mi++)
#pragma unroll
        for (int rr = 0; rr < 2; rr++) {
            const int row = warp_m + mi * 16 + rr * 8 + (lane >> 2);
#pragma unroll
            for (int ni = 0; ni < 8; ni++) {
                const int col = warp_n + ni * 8 + ((lane & 3) << 1);
                const float2 bv2 = *(const float2*)&bias[n0 + col];
                *(float2*)&Ef[row * ESTR4 + col] =
                    make_float2(acc[mi][ni][rr * 2 + 0] + bv2.x,
                                acc[mi][ni][rr * 2 + 1] + bv2.y);
            }
        }
    __syncthreads();
#pragma unroll
    for (int p = 0; p < 16; p++) {
        const int ml = p * 8 + (tid >> 5);
        float4 v = *(const float4*)&Ef[ml * ESTR4 + (tid & 31) * 4];
        *(float4*)&out[(size_t)(m0 + ml) * EMB + n0 + (tid & 31) * 4] = v;
    }
}

// ---------------------------------------------------------------------------
// Tensor-core attention: register softmax, V via ldmatrix.trans, staged
// coalesced writes for probs and ctx.
// ---------------------------------------------------------------------------
#define QS 72     // 64-wide bf16 tiles, stride 144 B
#define PS 136    // 128-wide bf16 tiles, stride 272 B

#define AOFF_QH  0
#define AOFF_QL  (AOFF_QH + 128 * QS * 2)    // 18432
#define AOFF_KH  (AOFF_QL + 128 * QS * 2)    // 36864
#define AOFF_KL  (AOFF_KH + 128 * QS * 2)    // 55296
#define AOFF_VH  (AOFF_KL + 128 * QS * 2)    // 73728
#define AOFF_VL  (AOFF_VH + 128 * QS * 2)    // 92160
#define AOFF_ST  (AOFF_VL + 128 * QS * 2)    // 110592 (sMax 256f, sSum 256f)
#define AOFF_MK  (AOFF_ST + 2048)            // 112640
#define ATTN_SMEM (AOFF_MK + 128)            // 112768 (2 CTA/SM: 225536<=227KB)
#define AOFF_PH  0                            // P overlays Q/K region
#define AOFF_PL  (AOFF_PH + 128 * PS * 2)    // 34816 (PH+PL=69632 < 73728)
#define AOFF_CH  0                            // ctx staging overlays P after PV
#define AOFF_CL  (AOFF_CH + 128 * QS * 2)    // 18432

__global__ __launch_bounds__(256, 2) void attn_mma(
    const bf16* __restrict__ qh, const bf16* __restrict__ ql,
    const bf16* __restrict__ kh, const bf16* __restrict__ kl,
    const bf16* __restrict__ vh, const bf16* __restrict__ vl,
    const unsigned char* __restrict__ mask,
    float* __restrict__ probs, int write_probs)
{
    extern __shared__ char dsm[];
    const uint32_t u0 = smem_u32(dsm);
    float* sMax = (float*)(dsm + AOFF_ST);
    float* sSum = sMax + 256;
    unsigned char* sMask = (unsigned char*)(dsm + AOFF_MK);

    const int c   = blockIdx.x;
    const int h   = blockIdx.y;
    const int tid = threadIdx.x;
    const int lane = tid & 31;
    const int wid  = tid >> 5;
    const size_t base = (((size_t)c * NH + h) * RR) * DKD;

    // ---- load all 6 tiles (128 rows x 64 bf16) via cp.async ----
    {
        const int row_q = tid >> 1;
        const int c16_q = tid & 1;
        const bf16* srcs[6] = {qh, ql, kh, kl, vh, vl};
        const uint32_t dsts[6] = {u0 + AOFF_QH, u0 + AOFF_QL,
                                  u0 + AOFF_KH, u0 + AOFF_KL,
                                  u0 + AOFF_VH, u0 + AOFF_VL};
#pragma unroll
        for (int t = 0; t < 6; t++) {
#pragma unroll
            for (int sub = 0; sub < 4; sub++) {
                const int cid = sub * 2 + c16_q;
                CP_ASYNC(dsts[t] + row_q * (QS * 2) + cid * 16,
                         srcs[t] + base + (size_t)row_q * DKD + cid * 8);
            }
        }
        CP_COMMIT();
        if (tid < 128) sMask[tid] = mask[(size_t)tid * CC + c];
        CP_WAIT(0);
    }
    __syncthreads();

    const int a_r = lane & 15;
    const int a_k = (lane >> 4) << 3;
    const int b_n = (lane & 7) + ((lane >> 4) << 3);
    const int b_k = ((lane >> 3) & 1) << 3;
    const int v_r = (((lane >> 3) & 1) << 3) + (lane & 7);  // trans: k-row
    const int v_c = (lane >> 4) << 3;                       // trans: n-col
    const int warp_m = (wid & 3) << 5;
    const int half   = wid >> 2;
    const int warp_n = half << 6;

    // ---- S = Q K^T (M=128, N=128, K=64), scores in registers ----
    float acc[2][8][4];
#pragma unroll
    for (int mi = 0; mi < 2; mi++)
#pragma unroll
        for (int ni = 0; ni < 8; ni++)
#pragma unroll
            for (int q = 0; q < 4; q++) acc[mi][ni][q] = 0.f;

#pragma unroll
    for (int ks = 0; ks < 4; ks++) {
        const int kk = ks << 4;
        uint32_t aH[2][4], aL[2][4];
#pragma unroll
        for (int mi = 0; mi < 2; mi++) {
            const uint32_t off =
                (uint32_t)((warp_m + mi * 16 + a_r) * QS + kk + a_k) * 2;
            ldsm4(aH[mi], u0 + AOFF_QH + off);
            ldsm4(aL[mi], u0 + AOFF_QL + off);
        }
#pragma unroll
        for (int np = 0; np < 4; np++) {
            uint32_t bH[4], bL[4];
            const uint32_t off =
                (uint32_t)((warp_n + np * 16 + b_n) * QS + kk + b_k) * 2;
            ldsm4(bH, u0 + AOFF_KH + off);
            ldsm4(bL, u0 + AOFF_KL + off);
#pragma unroll
            for (int mi = 0; mi < 2; mi++) {
#pragma unroll
                for (int ss = 0; ss < 2; ss++) {
                    float* cp = acc[mi][np * 2 + ss];
                    mma_bf16(cp, aH[mi], bH + 2 * ss);
                    mma_bf16(cp, aL[mi], bH + 2 * ss);
                    mma_bf16(cp, aH[mi], bL + 2 * ss);
                }
            }
        }
    }

    // ---- mask ----
#pragma unroll
    for (int ni = 0; ni < 8; ni++) {
        const int c0 = warp_n + ni * 8 + ((lane & 3) << 1);
        if (sMask[c0]) {
            acc[0][ni][0] = -10000.f; acc[0][ni][2] = -10000.f;
            acc[1][ni][0] = -10000.f; acc[1][ni][2] = -10000.f;
        }
        if (sMask[c0 + 1]) {
            acc[0][ni][1] = -10000.f; acc[0][ni][3] = -10000.f;
            acc[1][ni][1] = -10000.f; acc[1][ni][3] = -10000.f;
        }
    }

    // ---- row max ----
#pragma unroll
    for (int mi = 0; mi < 2; mi++)
#pragma unroll
        for (int rr = 0; rr < 2; rr++) {
            float mx = -1e30f;
#pragma unroll
            for (int ni = 0; ni < 8; ni++) {
                mx = fmaxf(mx, acc[mi][ni][rr * 2 + 0]);
                mx = fmaxf(mx, acc[mi][ni][rr * 2 + 1]);
            }
            mx = fmaxf(mx, __shfl_xor_sync(0xFFFFFFFFu, mx, 1));
            mx = fmaxf(mx, __shfl_xor_sync(0xFFFFFFFFu, mx, 2));
            const int row = warp_m + mi * 16 + rr * 8 + (lane >> 2);
            if ((lane & 3) == 0) sMax[half * 128 + row] = mx;
        }
    __syncthreads();

    // ---- exp + row sum ----
#pragma unroll
    for (int mi = 0; mi < 2; mi++)
#pragma unroll
        for (int rr = 0; rr < 2; rr++) {
            const int row = warp_m + mi * 16 + rr * 8 + (lane >> 2);
            const float m = fmaxf(sMax[row], sMax[128 + row]);
            float s = 0.f;
#pragma unroll
            for (int ni = 0; ni < 8; ni++) {
                float e0 = __expf(acc[mi][ni][rr * 2 + 0] - m);
                float e1 = __expf(acc[mi][ni][rr * 2 + 1] - m);
                acc[mi][ni][rr * 2 + 0] = e0;
                acc[mi][ni][rr * 2 + 1] = e1;
                s += e0 + e1;
            }
            s += __shfl_xor_sync(0xFFFFFFFFu, s, 1);
            s += __shfl_xor_sync(0xFFFFFFFFu, s, 2);
            if ((lane & 3) == 0) sSum[half * 128 + row] = s;
        }
    __syncthreads();

    // ---- normalize + split P to bf16 hi/lo in smem (overlay Q/K) ----
    {
        bf16* Ph = (bf16*)(dsm + AOFF_PH);
        bf16* Pl = (bf16*)(dsm + AOFF_PL);
#pragma unroll
        for (int mi = 0; mi < 2; mi++)
#pragma unroll
            for (int rr = 0; rr < 2; rr++) {
                const int row = warp_m + mi * 16 + rr * 8 + (lane >> 2);
                const float inv = 1.f / (sSum[row] + sSum[128 + row]);
#pragma unroll
                for (int ni = 0; ni < 8; ni++) {
                    const int col = warp_n + ni * 8 + ((lane & 3) << 1);
                    const float p0 = acc[mi][ni][rr * 2 + 0] * inv;
                    const float p1 = acc[mi][ni][rr * 2 + 1] * inv;
                    bf16 h0, l0, h1, l1;
                    split1(p0, h0, l0); split1(p1, h1, l1);
                    *(__nv_bfloat162*)&Ph[row * PS + col] = __halves2bfloat162(h0, h1);
                    *(__nv_bfloat162*)&Pl[row * PS + col] = __halves2bfloat162(l0, l1);
                }
            }
    }
    __syncthreads();

    // ---- coalesced probs write: p = hi + lo (error 2^-17) ----
    if (write_probs) {
        const bf16* Ph = (const bf16*)(dsm + AOFF_PH);
        const bf16* Pl = (const bf16*)(dsm + AOFF_PL);
        float* pb = probs + (((size_t)h * CC + c) * RR) * RR;
#pragma unroll
        for (int p = 0; p < 16; p++) {
            const int row = p * 8 + (tid >> 5);
            const int col = (lane) * 4;
            const __nv_bfloat162* hp = (const __nv_bfloat162*)&Ph[row * PS + col];
            const __nv_bfloat162* lp = (const __nv_bfloat162*)&Pl[row * PS + col];
            float2 h0 = __bfloat1622float2(hp[0]);
            float2 h1 = __bfloat1622float2(hp[1]);
            float2 l0 = __bfloat1622float2(lp[0]);
            float2 l1 = __bfloat1622float2(lp[1]);
            float4 v = make_float4(h0.x + l0.x, h0.y + l0.y,
                                   h1.x + l1.x, h1.y + l1.y);
            *(float4*)&pb[(size_t)row * RR + col] = v;
        }
    }

    // ---- ctx = P V (M=128, N=64, K=128); V B-frags via ldmatrix.trans ----
    float acc2[2][4][4];
#pragma unroll
    for (int mi = 0; mi < 2; mi++)
#pragma unroll
        for (int ni = 0; ni < 4; ni++)
#pragma unroll
            for (int q = 0; q < 4; q++) acc2[mi][ni][q] = 0.f;

    {
        const int warp_nd = half << 5;
#pragma unroll
        for (int ks = 0; ks < 8; ks++) {
            const int kk = ks << 4;
            uint32_t aH[2][4], aL[2][4];
#pragma unroll
            for (int mi = 0; mi < 2; mi++) {
                const uint32_t off =
                    (uint32_t)((warp_m + mi * 16 + a_r) * PS + kk + a_k) * 2;
                ldsm4(aH[mi], u0 + AOFF_PH + off);
                ldsm4(aL[mi], u0 + AOFF_PL + off);
            }
#pragma unroll
            for (int np = 0; np < 2; np++) {
                uint32_t bH[4], bL[4];
                const uint32_t off =
                    (uint32_t)((kk + v_r) * QS + warp_nd + np * 16 + v_c) * 2;
                ldsm4t(bH, u0 + AOFF_VH + off);
                ldsm4t(bL, u0 + AOFF_VL + off);
#pragma unroll
                for (int mi = 0; mi < 2; mi++) {
#pragma unroll
                    for (int ss = 0; ss < 2; ss++) {
                        float* cp = acc2[mi][np * 2 + ss];
                        mma_bf16(cp, aH[mi], bH + 2 * ss);
                        mma_bf16(cp, aH[mi], bL + 2 * ss);
                        mma_bf16(cp, aL[mi], bH + 2 * ss);
                    }
                }
            }
        }
    }
    __syncthreads();   // P and V reads done; reuse smem for ctx staging

    // ---- stage ctx hi/lo in smem, then coalesced write ----
    {
        bf16* Chs = (bf16*)(dsm + AOFF_CH);
        bf16* Cls = (bf16*)(dsm + AOFF_CL);
        const int warp_nd = half << 5;
#pragma unroll
        for (int mi = 0; mi < 2; mi++)
#pragma unroll
            for (int rr = 0; rr < 2; rr++) {
                const int i = warp_m + mi * 16 + rr * 8 + (lane >> 2);
#pragma unroll
                for (int ni = 0; ni < 4; ni++) {
                    const int d = warp_nd + ni * 8 + ((lane & 3) << 1);
                    bf16 h0, l0, h1, l1;
                    split1(acc2[mi][ni][rr * 2 + 0], h0, l0);
                    split1(acc2[mi][ni][rr * 2 + 1], h1, l1);
                    *(__nv_bfloat162*)&Chs[i * QS + d] = __halves2bfloat162(h0, h1);
                    *(__nv_bfloat162*)&Cls[i * QS + d] = __halves2bfloat162(l0, l1);
                }
            }
    }
    __syncthreads();
    {
        const bf16* Chs = (const bf16*)(dsm + AOFF_CH);
        const bf16* Cls = (const bf16*)(dsm + AOFF_CL);
#pragma unroll
        for (int p = 0; p < 8; p++) {
            const int lr = p * 32 + (tid >> 3);   // 0..255
            const int arr = lr >> 7;
            const int i = lr & 127;
            const bf16* src = arr ? Cls : Chs;
            uint4 v = *(const uint4*)&src[i * QS + (tid & 7) * 8];
            bf16* dst = arr ? g_Cl : g_Ch;
            *(uint4*)&dst[((size_t)i * CC + c) * EMB + h * DKD + (tid & 7) * 8] = v;
        }
    }
}

// ---------------------------------------------------------------------------
extern "C" void kernel_launch(void* const* d_in, const int* in_sizes, int n_in,
                              void* d_out, int out_size)
{
    const float*         x    = (const float*)d_in[0];
    const unsigned char* mask = (const unsigned char*)d_in[1];
    const float* Wq = (const float*)d_in[2];
    const float* bq = (const float*)d_in[3];
    const float* Wk = (const float*)d_in[4];
    const float* bk = (const float*)d_in[5];
    const float* Wv = (const float*)d_in[6];
    const float* bv = (const float*)d_in[7];
    const float* Wo = (const float*)d_in[8];
    const float* bo = (const float*)d_in[9];
    float* out = (float*)d_out;

    const long long OUT_E   = (long long)NT * EMB;
    const long long PROBS_E = (long long)NH * CC * RR * RR;

    float* probs = nullptr;
    int write_probs = 0;
    int do_output = 1;
    if ((long long)out_size >= OUT_E + PROBS_E) {
        probs = out + OUT_E;
        write_probs = 1;
    } else if ((long long)out_size == PROBS_E) {
        probs = out;
        write_probs = 1;
        do_output = 0;
    }

    void *xh, *xl, *wh, *wl, *qh_, *ql_, *kh_, *kl_, *vh_, *vl_, *ch, *cl;
    cudaGetSymbolAddress(&xh, g_Xh);  cudaGetSymbolAddress(&xl, g_Xl);
    cudaGetSymbolAddress(&wh, g_Wh);  cudaGetSymbolAddress(&wl, g_Wl);
    cudaGetSymbolAddress(&qh_, g_Qh); cudaGetSymbolAddress(&ql_, g_Ql);
    cudaGetSymbolAddress(&kh_, g_Kh); cudaGetSymbolAddress(&kl_, g_Kl);
    cudaGetSymbolAddress(&vh_, g_Vh); cudaGetSymbolAddress(&vl_, g_Vl);
    cudaGetSymbolAddress(&ch, g_Ch);  cudaGetSymbolAddress(&cl, g_Cl);

    bf16* Xh = (bf16*)xh; bf16* Xl = (bf16*)xl;
    bf16* Wh = (bf16*)wh; bf16* Wl = (bf16*)wl;
    const size_t WSZ = (size_t)EMB * EMB;

    static int attr_set = 0;
    if (!attr_set) {
        cudaFuncSetAttribute(gemm_qkv,
                             cudaFuncAttributeMaxDynamicSharedMemorySize, GEMM_SMEM);
        cudaFuncSetAttribute(gemm_o,
                             cudaFuncAttributeMaxDynamicSharedMemorySize, GEMM_SMEM);
        cudaFuncSetAttribute(attn_mma,
                             cudaFuncAttributeMaxDynamicSharedMemorySize, ATTN_SMEM);
        attr_set = 1;
    }

    split_kernel<<<(NT * EMB / 4 + 255) / 256, 256>>>(x, Xh, Xl, NT * EMB / 4);
    split_w4_kernel<<<dim3((unsigned)((WSZ / 4 + 255) / 256), 4), 256>>>(
        Wq, Wk, Wv, Wo, Wh, Wl, (int)(WSZ / 4));

    gemm_qkv<<<dim3(6, 256, 3), 256, GEMM_SMEM>>>(
        Xh, Xl, Wh, Wl, bq, bk, bv,
        (bf16*)qh_, (bf16*)ql_, (bf16*)kh_, (bf16*)kl_, (bf16*)vh_, (bf16*)vl_);

    attn_mma<<<dim3(CC, NH), 256, ATTN_SMEM>>>(
        (const bf16*)qh_, (const bf16*)ql_, (const bf16*)kh_, (const bf16*)kl_,
        (const bf16*)vh_, (const bf16*)vl_, mask, probs, write_probs);

    if (do_output)
        gemm_o<<<dim3(6, 256), 256, GEMM_SMEM>>>(
            (const bf16*)ch, (const bf16*)cl, Wh + 3 * WSZ, Wl + 3 * WSZ, bo, out);
}